// round 15
// baseline (speedup 1.0000x reference)
#include <cuda_runtime.h>
#include <cuda_bf16.h>
#include <math.h>
#include <stdint.h>

// ---------------- problem constants ----------------
#define Bx 2
#define Sx 1024
#define Dx 2048
#define Hx 16
#define Fx 8192
#define Mx 8192
#define HDx 128
#define BSx (Bx*Sx)   // 2048 token rows

// ---------------- scratch ----------------
__device__ float g_merged[BSx*Dx];
__device__ float g_q[BSx*Dx];
__device__ float g_k[BSx*Dx];
__device__ float g_v[BSx*Dx];
__device__ float g_ctx[BSx*Dx];
__device__ float g_xattn[BSx*Dx];
__device__ float g_gate[(size_t)BSx*Fx];
__device__ float g_up[(size_t)BSx*Fx];
__device__ unsigned long long g_knn[BSx];

// bf16 hi/lo splits
__device__ __align__(256) __nv_bfloat16 g_act_hi[(size_t)BSx*Fx];
__device__ __align__(256) __nv_bfloat16 g_act_lo[(size_t)BSx*Fx];
__device__ __align__(256) __nv_bfloat16 g_wqT_hi[Dx*Dx];
__device__ __align__(256) __nv_bfloat16 g_wqT_lo[Dx*Dx];
__device__ __align__(256) __nv_bfloat16 g_wkT_hi[Dx*Dx];
__device__ __align__(256) __nv_bfloat16 g_wkT_lo[Dx*Dx];
__device__ __align__(256) __nv_bfloat16 g_wvT_hi[Dx*Dx];
__device__ __align__(256) __nv_bfloat16 g_wvT_lo[Dx*Dx];
__device__ __align__(256) __nv_bfloat16 g_woT_hi[Dx*Dx];
__device__ __align__(256) __nv_bfloat16 g_woT_lo[Dx*Dx];
__device__ __align__(256) __nv_bfloat16 g_wgT_hi[(size_t)Fx*Dx];
__device__ __align__(256) __nv_bfloat16 g_wgT_lo[(size_t)Fx*Dx];
__device__ __align__(256) __nv_bfloat16 g_wuT_hi[(size_t)Fx*Dx];
__device__ __align__(256) __nv_bfloat16 g_wuT_lo[(size_t)Fx*Dx];
__device__ __align__(256) __nv_bfloat16 g_wdT_hi[(size_t)Dx*Fx];
__device__ __align__(256) __nv_bfloat16 g_wdT_lo[(size_t)Dx*Fx];

// ---------------- PTX helpers (baseline sm_80+ only) ----------------
__device__ __forceinline__ uint32_t smem_u32(const void* p) {
    uint32_t a;
    asm("{ .reg .u64 t; cvta.to.shared.u64 t, %1; cvt.u32.u64 %0, t; }"
        : "=r"(a) : "l"(p));
    return a;
}
__device__ __forceinline__ void cp_async16(uint32_t dst, const void* src) {
    asm volatile("cp.async.cg.shared.global [%0], [%1], 16;"
                 :: "r"(dst), "l"(src) : "memory");
}
#define CP_COMMIT() asm volatile("cp.async.commit_group;" ::: "memory")
#define CP_WAIT1()  asm volatile("cp.async.wait_group 1;" ::: "memory")

__device__ __forceinline__ void ldsm4(uint32_t* r, uint32_t addr) {
    asm volatile("ldmatrix.sync.aligned.m8n8.x4.shared.b16 {%0,%1,%2,%3}, [%4];"
                 : "=r"(r[0]), "=r"(r[1]), "=r"(r[2]), "=r"(r[3]) : "r"(addr));
}
__device__ __forceinline__ void mma_bf16(float* c, const uint32_t* a, const uint32_t* b) {
    asm volatile(
        "mma.sync.aligned.m16n8k16.row.col.f32.bf16.bf16.f32 "
        "{%0,%1,%2,%3}, {%4,%5,%6,%7}, {%8,%9}, {%0,%1,%2,%3};"
        : "+f"(c[0]), "+f"(c[1]), "+f"(c[2]), "+f"(c[3])
        : "r"(a[0]), "r"(a[1]), "r"(a[2]), "r"(a[3]), "r"(b[0]), "r"(b[1]));
}

// ---------------- kNN argmax reset ----------------
__global__ void reset_knn_kernel() {
    int i = blockIdx.x * blockDim.x + threadIdx.x;
    if (i < BSx) g_knn[i] = 0ULL;
}

// ---------------- kNN: scores = hs @ mem^T, fused row-argmax (fp32, exact) ----------------
__global__ void __launch_bounds__(256) knn_gemm_kernel(
    const float* __restrict__ A, const float* __restrict__ Bm)
{
    __shared__ __align__(16) float As[16][128];
    __shared__ __align__(16) float Bs[16][128];
    const int tid = threadIdx.x;
    const int tx = tid & 15, ty = tid >> 4;
    const int m0 = blockIdx.y * 128, n0 = blockIdx.x * 128;
    const int K = Dx;

    float acc[8][8];
#pragma unroll
    for (int i = 0; i < 8; i++)
#pragma unroll
        for (int j = 0; j < 8; j++) acc[i][j] = 0.f;

    for (int k0 = 0; k0 < K; k0 += 16) {
#pragma unroll
        for (int it = 0; it < 2; it++) {
            int e = tid + it * 256;
            int row = e >> 2;
            int c4 = e & 3;
            float4 v = *reinterpret_cast<const float4*>(
                &A[(size_t)(m0 + row) * K + k0 + c4 * 4]);
            As[c4*4+0][row] = v.x; As[c4*4+1][row] = v.y;
            As[c4*4+2][row] = v.z; As[c4*4+3][row] = v.w;
        }
#pragma unroll
        for (int it = 0; it < 2; it++) {
            int e = tid + it * 256;
            int row = e >> 2;
            int c4 = e & 3;
            float4 v = *reinterpret_cast<const float4*>(
                &Bm[(size_t)(n0 + row) * K + k0 + c4 * 4]);
            Bs[c4*4+0][row] = v.x; Bs[c4*4+1][row] = v.y;
            Bs[c4*4+2][row] = v.z; Bs[c4*4+3][row] = v.w;
        }
        __syncthreads();
#pragma unroll
        for (int kk = 0; kk < 16; kk++) {
            float a[8], b[8];
            float4 t0 = *reinterpret_cast<const float4*>(&As[kk][ty * 8]);
            float4 t1 = *reinterpret_cast<const float4*>(&As[kk][ty * 8 + 4]);
            a[0]=t0.x; a[1]=t0.y; a[2]=t0.z; a[3]=t0.w;
            a[4]=t1.x; a[5]=t1.y; a[6]=t1.z; a[7]=t1.w;
            float4 u0 = *reinterpret_cast<const float4*>(&Bs[kk][tx * 8]);
            float4 u1 = *reinterpret_cast<const float4*>(&Bs[kk][tx * 8 + 4]);
            b[0]=u0.x; b[1]=u0.y; b[2]=u0.z; b[3]=u0.w;
            b[4]=u1.x; b[5]=u1.y; b[6]=u1.z; b[7]=u1.w;
#pragma unroll
            for (int i = 0; i < 8; i++)
#pragma unroll
                for (int j = 0; j < 8; j++)
                    acc[i][j] = fmaf(a[i], b[j], acc[i][j]);
        }
        __syncthreads();
    }
#pragma unroll
    for (int i = 0; i < 8; i++) {
        float best = acc[i][0];
        int bcol = n0 + tx * 8;
#pragma unroll
        for (int j = 1; j < 8; j++) {
            float v = acc[i][j];
            int c = n0 + tx * 8 + j;
            if (v > best) { best = v; bcol = c; }
        }
#pragma unroll
        for (int off = 8; off >= 1; off >>= 1) {
            float ov = __shfl_xor_sync(0xffffffffu, best, off);
            int oc = __shfl_xor_sync(0xffffffffu, bcol, off);
            if (ov > best || (ov == best && oc < bcol)) { best = ov; bcol = oc; }
        }
        if (tx == 0) {
            unsigned ub = __float_as_uint(best);
            ub = (ub & 0x80000000u) ? ~ub : (ub | 0x80000000u);
            unsigned long long packed =
                ((unsigned long long)ub << 32) | (unsigned)(~bcol);
            atomicMax(&g_knn[m0 + ty * 8 + i], packed);
        }
    }
}

// ---------------- gated L2-normalized mix ----------------
__global__ void __launch_bounds__(256) mix_kernel(
    const float* __restrict__ hs, const float* __restrict__ mem,
    const float* __restrict__ gate_logit)
{
    int r = blockIdx.x;
    const float* hrow = hs + (size_t)r * Dx;
    unsigned idx = ~(unsigned)(g_knn[r] & 0xffffffffu);
    const float* mrow = mem + (size_t)idx * Dx;

    float sh = 0.f, sm = 0.f;
    for (int d = threadIdx.x; d < Dx; d += 256) {
        float a = hrow[d]; sh += a * a;
        float c = mrow[d]; sm += c * c;
    }
#pragma unroll
    for (int off = 16; off; off >>= 1) {
        sh += __shfl_xor_sync(0xffffffffu, sh, off);
        sm += __shfl_xor_sync(0xffffffffu, sm, off);
    }
    __shared__ float redh[8], redm[8];
    __shared__ float s_ratio;
    int lane = threadIdx.x & 31, wp = threadIdx.x >> 5;
    if (lane == 0) { redh[wp] = sh; redm[wp] = sm; }
    __syncthreads();
    if (threadIdx.x == 0) {
        float th = 0.f, tm = 0.f;
        for (int i = 0; i < 8; i++) { th += redh[i]; tm += redm[i]; }
        float nh = sqrtf(th) + 1e-4f;
        float nm = sqrtf(tm) + 1e-4f;
        s_ratio = nh / nm;
    }
    __syncthreads();
    float ratio = s_ratio;
    for (int d = threadIdx.x; d < Dx; d += 256) {
        float g = 1.f / (1.f + expf(-gate_logit[d]));
        g_merged[(size_t)r * Dx + d] = g * hrow[d] + (1.f - g) * mrow[d] * ratio;
    }
}

// ---------------- RMS norm with fused bf16 hi/lo split output ----------------
__global__ void __launch_bounds__(256) rmsnorm_split_kernel(
    const float* __restrict__ x, const float* __restrict__ w,
    __nv_bfloat16* __restrict__ hi, __nv_bfloat16* __restrict__ lo)
{
    int r = blockIdx.x;
    const float* row = x + (size_t)r * Dx;
    float ss = 0.f;
    for (int d = threadIdx.x; d < Dx; d += 256) { float a = row[d]; ss += a * a; }
#pragma unroll
    for (int off = 16; off; off >>= 1) ss += __shfl_xor_sync(0xffffffffu, ss, off);
    __shared__ float red[8];
    __shared__ float s_scale;
    int lane = threadIdx.x & 31, wp = threadIdx.x >> 5;
    if (lane == 0) red[wp] = ss;
    __syncthreads();
    if (threadIdx.x == 0) {
        float t = 0.f;
        for (int i = 0; i < 8; i++) t += red[i];
        s_scale = rsqrtf(t / (float)Dx + 1e-6f);
    }
    __syncthreads();
    float sc = s_scale;
    for (int d = threadIdx.x; d < Dx; d += 256) {
        float v = row[d] * sc * w[d];
        __nv_bfloat16 h = __float2bfloat16_rn(v);
        size_t o = (size_t)r * Dx + d;
        hi[o] = h;
        lo[o] = __float2bfloat16_rn(v - __bfloat162float(h));
    }
}

// ---------------- plain hi/lo split ----------------
__global__ void split_kernel(const float* __restrict__ x,
                             __nv_bfloat16* __restrict__ hi,
                             __nv_bfloat16* __restrict__ lo, int n)
{
    int i = blockIdx.x * blockDim.x + threadIdx.x;
    if (i >= n) return;
    float v = x[i];
    __nv_bfloat16 h = __float2bfloat16_rn(v);
    hi[i] = h;
    lo[i] = __float2bfloat16_rn(v - __bfloat162float(h));
}

// ---------------- transpose + split: W[K,N] -> T[N,K] hi/lo ----------------
__global__ void __launch_bounds__(256) transpose_split_kernel(
    const float* __restrict__ W, __nv_bfloat16* __restrict__ hiT,
    __nv_bfloat16* __restrict__ loT, int K, int N)
{
    __shared__ float tile[32][33];
    int n0 = blockIdx.x * 32, k0 = blockIdx.y * 32;
    int tx = threadIdx.x & 31, ty = threadIdx.x >> 5;  // 32x8
#pragma unroll
    for (int i = 0; i < 4; i++)
        tile[ty + i*8][tx] = W[(size_t)(k0 + ty + i*8) * N + n0 + tx];
    __syncthreads();
#pragma unroll
    for (int i = 0; i < 4; i++) {
        float v = tile[tx][ty + i*8];
        __nv_bfloat16 h = __float2bfloat16_rn(v);
        size_t o = (size_t)(n0 + ty + i*8) * K + k0 + tx;
        hiT[o] = h;
        loT[o] = __float2bfloat16_rn(v - __bfloat162float(h));
    }
}

// ---------------- HMMA bf16 3-pass GEMM (mma.sync, baseline PTX) ----------------
// C[.,N] = split(A) @ split(B^T)^T (+ addsrc). grid(N/128, M/128), 128 thr.
// CTA tile 128x128xBK64, 4 warps each 64x64. 3-stage cp.async pipeline.
#define GSTAGES 3
#define GSTAGE_BYTES 32768              // A 16KB + B 16KB (SW128 swizzled)
#define GS_SMEM (GSTAGES * GSTAGE_BYTES)
__global__ void __launch_bounds__(128) gemm_bf16_kernel(
    const __nv_bfloat16* __restrict__ Ahi, const __nv_bfloat16* __restrict__ Alo,
    const __nv_bfloat16* __restrict__ Bhi, const __nv_bfloat16* __restrict__ Blo,
    const float* __restrict__ addsrc, float* __restrict__ C, int N, int K)
{
    extern __shared__ __align__(128) char smem[];
    const uint32_t sb = smem_u32(smem);
    const int tid = threadIdx.x;
    const int lane = tid & 31, wid = tid >> 5;
    const int wm = wid & 1, wn = wid >> 1;      // 2x2 warp grid, 64x64 each
    const int m0 = blockIdx.y * 128, n0 = blockIdx.x * 128;

    const int nk = K >> 6;
    const int nch = 3 * nk;
    const __nv_bfloat16* APs[3] = {Ahi, Ahi, Alo};
    const __nv_bfloat16* BPs[3] = {Bhi, Blo, Bhi};

    float acc[4][8][4];
#pragma unroll
    for (int mt = 0; mt < 4; mt++)
#pragma unroll
        for (int nt = 0; nt < 8; nt++)
#pragma unroll
            for (int t = 0; t < 4; t++) acc[mt][nt][t] = 0.f;

    // ---- copy mapping: thread owns 16B block cblk of rows crow0+16i ----
    const int cblk = tid & 7, crow0 = tid >> 3;
    const uint32_t dblk = (uint32_t)((cblk ^ (crow0 & 7)) << 4);  // row&7 const mod 16

    // ---- ldmatrix address parts ----
    uint32_t arow[4], brow[4];
    const int hiA = lane >> 4;                  // k8-half select for A
    const int xa_base = wm * 64 + (lane & 15);
#pragma unroll
    for (int mt = 0; mt < 4; mt++) arow[mt] = (uint32_t)((xa_base + mt * 16) * 128);
    const uint32_t xa = (uint32_t)(xa_base & 7);
    const int rB0 = wn * 64 + (lane & 7) + (lane >> 4) * 8;
    const int khB = (lane >> 3) & 1;
#pragma unroll
    for (int j = 0; j < 4; j++) brow[j] = (uint32_t)((rB0 + j * 16) * 128);
    const uint32_t xb = (uint32_t)(rB0 & 7);

    // ---- chunk loader ----
    auto load_chunk = [&](int c) {
        int p = c / nk, kc = c - p * nk;
        const __nv_bfloat16* Ap = APs[p] + (size_t)kc * 64 + cblk * 8;
        const __nv_bfloat16* Bp = BPs[p] + (size_t)kc * 64 + cblk * 8;
        uint32_t st = sb + (uint32_t)(c % GSTAGES) * GSTAGE_BYTES;
#pragma unroll
        for (int i = 0; i < 8; i++) {
            int row = crow0 + 16 * i;
            uint32_t d = st + (uint32_t)(row * 128) + dblk;
            cp_async16(d,         Ap + (size_t)(m0 + row) * K);
            cp_async16(d + 16384, Bp + (size_t)(n0 + row) * K);
        }
        CP_COMMIT();
    };

    load_chunk(0);
    load_chunk(1);

    for (int c = 0; c < nch; c++) {
        CP_WAIT1();
        __syncthreads();
        if (c + 2 < nch) load_chunk(c + 2); else CP_COMMIT();

        uint32_t stA = sb + (uint32_t)(c % GSTAGES) * GSTAGE_BYTES;
        uint32_t stB = stA + 16384;
#pragma unroll
        for (int k16 = 0; k16 < 4; k16++) {
            uint32_t a[4][4], b[4][4];
#pragma unroll
            for (int mt = 0; mt < 4; mt++)
                ldsm4(a[mt], stA + arow[mt] +
                      ((((uint32_t)(k16 << 1) | (uint32_t)hiA) ^ xa) << 4));
#pragma unroll
            for (int j = 0; j < 4; j++)
                ldsm4(b[j], stB + brow[j] +
                      ((((uint32_t)(k16 << 1) | (uint32_t)khB) ^ xb) << 4));
#pragma unroll
            for (int mt = 0; mt < 4; mt++)
#pragma unroll
                for (int nt = 0; nt < 8; nt++)
                    mma_bf16(acc[mt][nt], a[mt], &b[nt >> 1][(nt & 1) * 2]);
        }
        __syncthreads();
    }

    // ---- epilogue ----
#pragma unroll
    for (int mt = 0; mt < 4; mt++) {
        int r0 = m0 + wm * 64 + mt * 16 + (lane >> 2);
#pragma unroll
        for (int nt = 0; nt < 8; nt++) {
            int cix = n0 + wn * 64 + nt * 8 + (lane & 3) * 2;
            float2 v0 = make_float2(acc[mt][nt][0], acc[mt][nt][1]);
            float2 v1 = make_float2(acc[mt][nt][2], acc[mt][nt][3]);
            size_t o0 = (size_t)r0 * N + cix;
            size_t o1 = (size_t)(r0 + 8) * N + cix;
            if (addsrc) {
                float2 a0 = *reinterpret_cast<const float2*>(addsrc + o0);
                float2 a1 = *reinterpret_cast<const float2*>(addsrc + o1);
                v0.x += a0.x; v0.y += a0.y;
                v1.x += a1.x; v1.y += a1.y;
            }
            *reinterpret_cast<float2*>(C + o0) = v0;
            *reinterpret_cast<float2*>(C + o1) = v1;
        }
    }
}

// ---------------- RoPE on q,k (layout [BS, H, HD]) ----------------
__global__ void rope_kernel(const int* __restrict__ pos_ids)
{
    int i = blockIdx.x * blockDim.x + threadIdx.x;
    const int total = BSx * Hx * 64;
    if (i >= total) return;
    int d = i & 63;
    int h = (i >> 6) & (Hx - 1);
    int r = i >> 10;
    float p = (float)pos_ids[r];
    float inv = powf(10000.f, -(float)d * (1.f / 64.f));
    float a = p * inv;
    float sn, cs;
    sincosf(a, &sn, &cs);
    size_t base = ((size_t)r * Hx + h) * HDx;
    float q1 = g_q[base + d], q2 = g_q[base + d + 64];
    g_q[base + d]      = q1 * cs - q2 * sn;
    g_q[base + d + 64] = q2 * cs + q1 * sn;
    float k1 = g_k[base + d], k2 = g_k[base + d + 64];
    g_k[base + d]      = k1 * cs - k2 * sn;
    g_k[base + d + 64] = k2 * cs + k1 * sn;
}

// ---------------- flash attention (fp32, causal) ----------------
#define AT_STRIDE 132
#define AT_SMEM_FLOATS (3*64*AT_STRIDE + 64*65)
__global__ void __launch_bounds__(256) attn_kernel()
{
    extern __shared__ __align__(16) float smemf[];
    float* Qs = smemf;
    float* Ks = Qs + 64 * AT_STRIDE;
    float* Vs = Ks + 64 * AT_STRIDE;
    float* Ps = Vs + 64 * AT_STRIDE;

    const int tid = threadIdx.x;
    const int qt = blockIdx.x, h = blockIdx.y, b = blockIdx.z;
    const int q0 = qt * 64;
    const int qr = tid >> 2;
    const int j = tid & 3;
    const float scale = 0.08838834764831845f;

    {
        const float* src = g_q + (((size_t)(b * Sx + q0)) * Hx + h) * HDx;
#pragma unroll
        for (int it = 0; it < 8; it++) {
            int e = tid + it * 256;
            int row = e >> 5, c4 = e & 31;
            *reinterpret_cast<float4*>(&Qs[row * AT_STRIDE + c4 * 4]) =
                *reinterpret_cast<const float4*>(src + (size_t)row * Dx + c4 * 4);
        }
    }
    float o[32];
#pragma unroll
    for (int t = 0; t < 32; t++) o[t] = 0.f;
    float mrow = -3.0e38f, lrow = 0.f;

    for (int kt = 0; kt <= qt; kt++) {
        __syncthreads();
        const float* ksrc = g_k + (((size_t)(b * Sx + kt * 64)) * Hx + h) * HDx;
        const float* vsrc = g_v + (((size_t)(b * Sx + kt * 64)) * Hx + h) * HDx;
#pragma unroll
        for (int it = 0; it < 8; it++) {
            int e = tid + it * 256;
            int row = e >> 5, c4 = e & 31;
            *reinterpret_cast<float4*>(&Ks[row * AT_STRIDE + c4 * 4]) =
                *reinterpret_cast<const float4*>(ksrc + (size_t)row * Dx + c4 * 4);
            *reinterpret_cast<float4*>(&Vs[row * AT_STRIDE + c4 * 4]) =
                *reinterpret_cast<const float4*>(vsrc + (size_t)row * Dx + c4 * 4);
        }
        __syncthreads();

        float s[16];
#pragma unroll
        for (int kk = 0; kk < 16; kk++) s[kk] = 0.f;
        const float4* Q4 = reinterpret_cast<const float4*>(Qs + qr * AT_STRIDE);
#pragma unroll 8
        for (int d4 = 0; d4 < 32; d4++) {
            float4 qv = Q4[d4];
#pragma unroll
            for (int kk = 0; kk < 16; kk++) {
                float4 kv = *reinterpret_cast<const float4*>(
                    &Ks[(j * 16 + kk) * AT_STRIDE + d4 * 4]);
                s[kk] = fmaf(qv.x, kv.x, s[kk]);
                s[kk] = fmaf(qv.y, kv.y, s[kk]);
                s[kk] = fmaf(qv.z, kv.z, s[kk]);
                s[kk] = fmaf(qv.w, kv.w, s[kk]);
            }
        }
        const int qg = q0 + qr;
        float mloc = -3.0e38f;
#pragma unroll
        for (int kk = 0; kk < 16; kk++) {
            int kg = kt * 64 + j * 16 + kk;
            s[kk] = (kg <= qg) ? s[kk] * scale : -3.0e38f;
            mloc = fmaxf(mloc, s[kk]);
        }
        mloc = fmaxf(mloc, __shfl_xor_sync(0xffffffffu, mloc, 1));
        mloc = fmaxf(mloc, __shfl_xor_sync(0xffffffffu, mloc, 2));
        float mnew = fmaxf(mrow, mloc);
        float lloc = 0.f;
#pragma unroll
        for (int kk = 0; kk < 16; kk++) {
            float pv = expf(s[kk] - mnew);
            Ps[qr * 65 + j * 16 + kk] = pv;
            lloc += pv;
        }
        lloc += __shfl_xor_sync(0xffffffffu, lloc, 1);
        lloc += __shfl_xor_sync(0xffffffffu, lloc, 2);
        float corr = expf(mrow - mnew);
        lrow = lrow * corr + lloc;
        mrow = mnew;
#pragma unroll
        for (int t = 0; t < 32; t++) o[t] *= corr;
        __syncthreads();
        const int dbase = j * 32;
#pragma unroll 4
        for (int k = 0; k < 64; k++) {
            float pv = Ps[qr * 65 + k];
            const float4* V4 = reinterpret_cast<const float4*>(
                &Vs[k * AT_STRIDE + dbase]);
#pragma unroll
            for (int t = 0; t < 8; t++) {
                float4 vv = V4[t];
                o[t*4+0] = fmaf(pv, vv.x, o[t*4+0]);
                o[t*4+1] = fmaf(pv, vv.y, o[t*4+1]);
                o[t*4+2] = fmaf(pv, vv.z, o[t*4+2]);
                o[t*4+3] = fmaf(pv, vv.w, o[t*4+3]);
            }
        }
    }
    float invl = 1.f / lrow;
    float* dst = g_ctx + (((size_t)(b * Sx + q0 + qr)) * Hx + h) * HDx + j * 32;
#pragma unroll
    for (int t = 0; t < 8; t++) {
        float4 v;
        v.x = o[t*4+0] * invl; v.y = o[t*4+1] * invl;
        v.z = o[t*4+2] * invl; v.w = o[t*4+3] * invl;
        *reinterpret_cast<float4*>(dst + t * 4) = v;
    }
}

// ---------------- silu(gate)*up with fused hi/lo split ----------------
__global__ void silu_mul_split_kernel()
{
    int i = blockIdx.x * blockDim.x + threadIdx.x;
    float g = g_gate[i];
    float u = g_up[i];
    float v = g / (1.f + expf(-g)) * u;
    __nv_bfloat16 h = __float2bfloat16_rn(v);
    g_act_hi[i] = h;
    g_act_lo[i] = __float2bfloat16_rn(v - __bfloat162float(h));
}

// ---------------- launch ----------------
extern "C" void kernel_launch(void* const* d_in, const int* in_sizes, int n_in,
                              void* d_out, int out_size)
{
    (void)in_sizes; (void)n_in; (void)out_size;
    const float* hs        = (const float*)d_in[0];
    const int*   pos       = (const int*)  d_in[1];
    const float* mem       = (const float*)d_in[2];
    const float* gatelogit = (const float*)d_in[3];
    const float* wq        = (const float*)d_in[4];
    const float* wk        = (const float*)d_in[5];
    const float* wv        = (const float*)d_in[6];
    const float* wo        = (const float*)d_in[7];
    const float* wg        = (const float*)d_in[8];
    const float* wu        = (const float*)d_in[9];
    const float* wd        = (const float*)d_in[10];
    const float* r1        = (const float*)d_in[11];
    const float* r2        = (const float*)d_in[12];
    float* out = (float*)d_out;

    float *merged, *q, *k, *v, *ctx, *xattn, *gbuf, *ubuf;
    cudaGetSymbolAddress((void**)&merged, g_merged);
    cudaGetSymbolAddress((void**)&q,      g_q);
    cudaGetSymbolAddress((void**)&k,      g_k);
    cudaGetSymbolAddress((void**)&v,      g_v);
    cudaGetSymbolAddress((void**)&ctx,    g_ctx);
    cudaGetSymbolAddress((void**)&xattn,  g_xattn);
    cudaGetSymbolAddress((void**)&gbuf,   g_gate);
    cudaGetSymbolAddress((void**)&ubuf,   g_up);
    __nv_bfloat16 *ah, *al;
    cudaGetSymbolAddress((void**)&ah, g_act_hi);
    cudaGetSymbolAddress((void**)&al, g_act_lo);
    __nv_bfloat16 *wqh,*wql,*wkh,*wkl,*wvh,*wvl,*woh,*wol,*wgh,*wgl,*wuh,*wul,*wdh,*wdl;
    cudaGetSymbolAddress((void**)&wqh, g_wqT_hi); cudaGetSymbolAddress((void**)&wql, g_wqT_lo);
    cudaGetSymbolAddress((void**)&wkh, g_wkT_hi); cudaGetSymbolAddress((void**)&wkl, g_wkT_lo);
    cudaGetSymbolAddress((void**)&wvh, g_wvT_hi); cudaGetSymbolAddress((void**)&wvl, g_wvT_lo);
    cudaGetSymbolAddress((void**)&woh, g_woT_hi); cudaGetSymbolAddress((void**)&wol, g_woT_lo);
    cudaGetSymbolAddress((void**)&wgh, g_wgT_hi); cudaGetSymbolAddress((void**)&wgl, g_wgT_lo);
    cudaGetSymbolAddress((void**)&wuh, g_wuT_hi); cudaGetSymbolAddress((void**)&wul, g_wuT_lo);
    cudaGetSymbolAddress((void**)&wdh, g_wdT_hi); cudaGetSymbolAddress((void**)&wdl, g_wdT_lo);

    cudaFuncSetAttribute(gemm_bf16_kernel,
                         cudaFuncAttributeMaxDynamicSharedMemorySize, GS_SMEM);
    const int att_smem = AT_SMEM_FLOATS * (int)sizeof(float);
    cudaFuncSetAttribute(attn_kernel,
                         cudaFuncAttributeMaxDynamicSharedMemorySize, att_smem);

    // 0. weight transpose + bf16 hi/lo split
    transpose_split_kernel<<<dim3(Dx/32, Dx/32), 256>>>(wq, wqh, wql, Dx, Dx);
    transpose_split_kernel<<<dim3(Dx/32, Dx/32), 256>>>(wk, wkh, wkl, Dx, Dx);
    transpose_split_kernel<<<dim3(Dx/32, Dx/32), 256>>>(wv, wvh, wvl, Dx, Dx);
    transpose_split_kernel<<<dim3(Dx/32, Dx/32), 256>>>(wo, woh, wol, Dx, Dx);
    transpose_split_kernel<<<dim3(Fx/32, Dx/32), 256>>>(wg, wgh, wgl, Dx, Fx);
    transpose_split_kernel<<<dim3(Fx/32, Dx/32), 256>>>(wu, wuh, wul, Dx, Fx);
    transpose_split_kernel<<<dim3(Dx/32, Fx/32), 256>>>(wd, wdh, wdl, Fx, Dx);

    // 1. kNN retrieval (fp32 GEMM-NT + fused argmax)
    reset_knn_kernel<<<8, 256>>>();
    knn_gemm_kernel<<<dim3(Mx/128, BSx/128), 256>>>(hs, mem);

    // 2. gated L2 mix
    mix_kernel<<<BSx, 256>>>(hs, mem, gatelogit);

    // 3. RMS norm 1 -> act splits
    rmsnorm_split_kernel<<<BSx, 256>>>(merged, r1, ah, al);

    // 4. QKV projections (HMMA)
    gemm_bf16_kernel<<<dim3(Dx/128, BSx/128), 128, GS_SMEM>>>(ah, al, wqh, wql, nullptr, q, Dx, Dx);
    gemm_bf16_kernel<<<dim3(Dx/128, BSx/128), 128, GS_SMEM>>>(ah, al, wkh, wkl, nullptr, k, Dx, Dx);
    gemm_bf16_kernel<<<dim3(Dx/128, BSx/128), 128, GS_SMEM>>>(ah, al, wvh, wvl, nullptr, v, Dx, Dx);

    // 5. RoPE
    rope_kernel<<<(BSx * Hx * 64) / 256, 256>>>(pos);

    // 6. flash attention
    attn_kernel<<<dim3(Sx/64, Hx, Bx), 256, att_smem>>>();

    // 7. output projection + residual
    split_kernel<<<(BSx*Dx)/256, 256>>>(ctx, ah, al, BSx*Dx);
    gemm_bf16_kernel<<<dim3(Dx/128, BSx/128), 128, GS_SMEM>>>(ah, al, woh, wol, merged, xattn, Dx, Dx);

    // 8. RMS norm 2 -> act splits
    rmsnorm_split_kernel<<<BSx, 256>>>(xattn, r2, ah, al);

    // 9. MLP (HMMA)
    gemm_bf16_kernel<<<dim3(Fx/128, BSx/128), 128, GS_SMEM>>>(ah, al, wgh, wgl, nullptr, gbuf, Fx, Dx);
    gemm_bf16_kernel<<<dim3(Fx/128, BSx/128), 128, GS_SMEM>>>(ah, al, wuh, wul, nullptr, ubuf, Fx, Dx);
    silu_mul_split_kernel<<<(int)(((size_t)BSx*Fx)/256), 256>>>();
    gemm_bf16_kernel<<<dim3(Dx/128, BSx/128), 128, GS_SMEM>>>(ah, al, wdh, wdl, xattn, out, Dx, Fx);
}

// round 16
// speedup vs baseline: 1.1812x; 1.1812x over previous
#include <cuda_runtime.h>
#include <cuda_bf16.h>
#include <math.h>
#include <stdint.h>

// ---------------- problem constants ----------------
#define Bx 2
#define Sx 1024
#define Dx 2048
#define Hx 16
#define Fx 8192
#define Mx 8192
#define HDx 128
#define BSx (Bx*Sx)   // 2048 token rows

// ---------------- scratch ----------------
__device__ float g_merged[BSx*Dx];
__device__ float g_q[BSx*Dx];
__device__ float g_k[BSx*Dx];
__device__ float g_v[BSx*Dx];
__device__ float g_ctx[BSx*Dx];
__device__ float g_xattn[BSx*Dx];
__device__ float g_gate[(size_t)BSx*Fx];
__device__ float g_up[(size_t)BSx*Fx];
__device__ int g_nn_idx[BSx];
__device__ unsigned long long g_cand[(size_t)BSx * (Mx/128)];

// bf16 hi/lo splits
__device__ __align__(256) __nv_bfloat16 g_act_hi[(size_t)BSx*Fx];
__device__ __align__(256) __nv_bfloat16 g_act_lo[(size_t)BSx*Fx];
__device__ __align__(256) __nv_bfloat16 g_mem_hi[(size_t)Mx*Dx];
__device__ __align__(256) __nv_bfloat16 g_mem_lo[(size_t)Mx*Dx];
__device__ __align__(256) __nv_bfloat16 g_wqT_hi[Dx*Dx];
__device__ __align__(256) __nv_bfloat16 g_wqT_lo[Dx*Dx];
__device__ __align__(256) __nv_bfloat16 g_wkT_hi[Dx*Dx];
__device__ __align__(256) __nv_bfloat16 g_wkT_lo[Dx*Dx];
__device__ __align__(256) __nv_bfloat16 g_wvT_hi[Dx*Dx];
__device__ __align__(256) __nv_bfloat16 g_wvT_lo[Dx*Dx];
__device__ __align__(256) __nv_bfloat16 g_woT_hi[Dx*Dx];
__device__ __align__(256) __nv_bfloat16 g_woT_lo[Dx*Dx];
__device__ __align__(256) __nv_bfloat16 g_wgT_hi[(size_t)Fx*Dx];
__device__ __align__(256) __nv_bfloat16 g_wgT_lo[(size_t)Fx*Dx];
__device__ __align__(256) __nv_bfloat16 g_wuT_hi[(size_t)Fx*Dx];
__device__ __align__(256) __nv_bfloat16 g_wuT_lo[(size_t)Fx*Dx];
__device__ __align__(256) __nv_bfloat16 g_wdT_hi[(size_t)Dx*Fx];
__device__ __align__(256) __nv_bfloat16 g_wdT_lo[(size_t)Dx*Fx];

// ---------------- PTX helpers (baseline sm_80+ only) ----------------
__device__ __forceinline__ uint32_t smem_u32(const void* p) {
    uint32_t a;
    asm("{ .reg .u64 t; cvta.to.shared.u64 t, %1; cvt.u32.u64 %0, t; }"
        : "=r"(a) : "l"(p));
    return a;
}
__device__ __forceinline__ void cp_async16(uint32_t dst, const void* src) {
    asm volatile("cp.async.cg.shared.global [%0], [%1], 16;"
                 :: "r"(dst), "l"(src) : "memory");
}
#define CP_COMMIT() asm volatile("cp.async.commit_group;" ::: "memory")
#define CP_WAIT1()  asm volatile("cp.async.wait_group 1;" ::: "memory")
#define CP_WAIT0()  asm volatile("cp.async.wait_group 0;" ::: "memory")

__device__ __forceinline__ void ldsm4(uint32_t* r, uint32_t addr) {
    asm volatile("ldmatrix.sync.aligned.m8n8.x4.shared.b16 {%0,%1,%2,%3}, [%4];"
                 : "=r"(r[0]), "=r"(r[1]), "=r"(r[2]), "=r"(r[3]) : "r"(addr));
}
__device__ __forceinline__ void mma_bf16(float* c, const uint32_t* a, const uint32_t* b) {
    asm volatile(
        "mma.sync.aligned.m16n8k16.row.col.f32.bf16.bf16.f32 "
        "{%0,%1,%2,%3}, {%4,%5,%6,%7}, {%8,%9}, {%0,%1,%2,%3};"
        : "+f"(c[0]), "+f"(c[1]), "+f"(c[2]), "+f"(c[3])
        : "r"(a[0]), "r"(a[1]), "r"(a[2]), "r"(a[3]), "r"(b[0]), "r"(b[1]));
}
__device__ __forceinline__ float unflip_score(uint32_t u) {
    return __uint_as_float((u & 0x80000000u) ? (u ^ 0x80000000u) : ~u);
}

// ---------------- gated L2-normalized mix ----------------
__global__ void __launch_bounds__(256) mix_kernel(
    const float* __restrict__ hs, const float* __restrict__ mem,
    const float* __restrict__ gate_logit)
{
    int r = blockIdx.x;
    const float* hrow = hs + (size_t)r * Dx;
    int idx = g_nn_idx[r];
    const float* mrow = mem + (size_t)idx * Dx;

    float sh = 0.f, sm = 0.f;
    for (int d = threadIdx.x; d < Dx; d += 256) {
        float a = hrow[d]; sh += a * a;
        float c = mrow[d]; sm += c * c;
    }
#pragma unroll
    for (int off = 16; off; off >>= 1) {
        sh += __shfl_xor_sync(0xffffffffu, sh, off);
        sm += __shfl_xor_sync(0xffffffffu, sm, off);
    }
    __shared__ float redh[8], redm[8];
    __shared__ float s_ratio;
    int lane = threadIdx.x & 31, wp = threadIdx.x >> 5;
    if (lane == 0) { redh[wp] = sh; redm[wp] = sm; }
    __syncthreads();
    if (threadIdx.x == 0) {
        float th = 0.f, tm = 0.f;
        for (int i = 0; i < 8; i++) { th += redh[i]; tm += redm[i]; }
        float nh = sqrtf(th) + 1e-4f;
        float nm = sqrtf(tm) + 1e-4f;
        s_ratio = nh / nm;
    }
    __syncthreads();
    float ratio = s_ratio;
    for (int d = threadIdx.x; d < Dx; d += 256) {
        float g = 1.f / (1.f + expf(-gate_logit[d]));
        g_merged[(size_t)r * Dx + d] = g * hrow[d] + (1.f - g) * mrow[d] * ratio;
    }
}

// ---------------- RMS norm with fused bf16 hi/lo split output ----------------
__global__ void __launch_bounds__(256) rmsnorm_split_kernel(
    const float* __restrict__ x, const float* __restrict__ w,
    __nv_bfloat16* __restrict__ hi, __nv_bfloat16* __restrict__ lo)
{
    int r = blockIdx.x;
    const float* row = x + (size_t)r * Dx;
    float ss = 0.f;
    for (int d = threadIdx.x; d < Dx; d += 256) { float a = row[d]; ss += a * a; }
#pragma unroll
    for (int off = 16; off; off >>= 1) ss += __shfl_xor_sync(0xffffffffu, ss, off);
    __shared__ float red[8];
    __shared__ float s_scale;
    int lane = threadIdx.x & 31, wp = threadIdx.x >> 5;
    if (lane == 0) red[wp] = ss;
    __syncthreads();
    if (threadIdx.x == 0) {
        float t = 0.f;
        for (int i = 0; i < 8; i++) t += red[i];
        s_scale = rsqrtf(t / (float)Dx + 1e-6f);
    }
    __syncthreads();
    float sc = s_scale;
    for (int d = threadIdx.x; d < Dx; d += 256) {
        float v = row[d] * sc * w[d];
        __nv_bfloat16 h = __float2bfloat16_rn(v);
        size_t o = (size_t)r * Dx + d;
        hi[o] = h;
        lo[o] = __float2bfloat16_rn(v - __bfloat162float(h));
    }
}

// ---------------- plain hi/lo split ----------------
__global__ void split_kernel(const float* __restrict__ x,
                             __nv_bfloat16* __restrict__ hi,
                             __nv_bfloat16* __restrict__ lo, int n)
{
    int i = blockIdx.x * blockDim.x + threadIdx.x;
    if (i >= n) return;
    float v = x[i];
    __nv_bfloat16 h = __float2bfloat16_rn(v);
    hi[i] = h;
    lo[i] = __float2bfloat16_rn(v - __bfloat162float(h));
}

// ---------------- transpose + split: W[K,N] -> T[N,K] hi/lo ----------------
__global__ void __launch_bounds__(256) transpose_split_kernel(
    const float* __restrict__ W, __nv_bfloat16* __restrict__ hiT,
    __nv_bfloat16* __restrict__ loT, int K, int N)
{
    __shared__ float tile[32][33];
    int n0 = blockIdx.x * 32, k0 = blockIdx.y * 32;
    int tx = threadIdx.x & 31, ty = threadIdx.x >> 5;  // 32x8
#pragma unroll
    for (int i = 0; i < 4; i++)
        tile[ty + i*8][tx] = W[(size_t)(k0 + ty + i*8) * N + n0 + tx];
    __syncthreads();
#pragma unroll
    for (int i = 0; i < 4; i++) {
        float v = tile[tx][ty + i*8];
        __nv_bfloat16 h = __float2bfloat16_rn(v);
        size_t o = (size_t)(n0 + ty + i*8) * K + k0 + tx;
        hiT[o] = h;
        loT[o] = __float2bfloat16_rn(v - __bfloat162float(h));
    }
}

// ---------------- HMMA bf16 3-pass GEMM (mma.sync, baseline PTX) ----------------
#define GSTAGES 3
#define GSTAGE_BYTES 32768              // A 16KB + B 16KB (SW128 swizzled)
#define GS_SMEM (GSTAGES * GSTAGE_BYTES)
__global__ void __launch_bounds__(128) gemm_bf16_kernel(
    const __nv_bfloat16* __restrict__ Ahi, const __nv_bfloat16* __restrict__ Alo,
    const __nv_bfloat16* __restrict__ Bhi, const __nv_bfloat16* __restrict__ Blo,
    const float* __restrict__ addsrc, float* __restrict__ C, int N, int K)
{
    extern __shared__ __align__(128) char smem[];
    const uint32_t sb = smem_u32(smem);
    const int tid = threadIdx.x;
    const int lane = tid & 31, wid = tid >> 5;
    const int wm = wid & 1, wn = wid >> 1;
    const int m0 = blockIdx.y * 128, n0 = blockIdx.x * 128;

    const int nk = K >> 6;
    const int nch = 3 * nk;
    const __nv_bfloat16* APs[3] = {Ahi, Ahi, Alo};
    const __nv_bfloat16* BPs[3] = {Bhi, Blo, Bhi};

    float acc[4][8][4];
#pragma unroll
    for (int mt = 0; mt < 4; mt++)
#pragma unroll
        for (int nt = 0; nt < 8; nt++)
#pragma unroll
            for (int t = 0; t < 4; t++) acc[mt][nt][t] = 0.f;

    const int cblk = tid & 7, crow0 = tid >> 3;
    const uint32_t dblk = (uint32_t)((cblk ^ (crow0 & 7)) << 4);

    uint32_t arow[4], brow[4];
    const int hiA = lane >> 4;
    const int xa_base = wm * 64 + (lane & 15);
#pragma unroll
    for (int mt = 0; mt < 4; mt++) arow[mt] = (uint32_t)((xa_base + mt * 16) * 128);
    const uint32_t xa = (uint32_t)(xa_base & 7);
    const int rB0 = wn * 64 + (lane & 7) + (lane >> 4) * 8;
    const int khB = (lane >> 3) & 1;
#pragma unroll
    for (int j = 0; j < 4; j++) brow[j] = (uint32_t)((rB0 + j * 16) * 128);
    const uint32_t xb = (uint32_t)(rB0 & 7);

    auto load_chunk = [&](int c) {
        int p = c / nk, kc = c - p * nk;
        const __nv_bfloat16* Ap = APs[p] + (size_t)kc * 64 + cblk * 8;
        const __nv_bfloat16* Bp = BPs[p] + (size_t)kc * 64 + cblk * 8;
        uint32_t st = sb + (uint32_t)(c % GSTAGES) * GSTAGE_BYTES;
#pragma unroll
        for (int i = 0; i < 8; i++) {
            int row = crow0 + 16 * i;
            uint32_t d = st + (uint32_t)(row * 128) + dblk;
            cp_async16(d,         Ap + (size_t)(m0 + row) * K);
            cp_async16(d + 16384, Bp + (size_t)(n0 + row) * K);
        }
        CP_COMMIT();
    };

    load_chunk(0);
    load_chunk(1);

    for (int c = 0; c < nch; c++) {
        CP_WAIT1();
        __syncthreads();
        if (c + 2 < nch) load_chunk(c + 2); else CP_COMMIT();

        uint32_t stA = sb + (uint32_t)(c % GSTAGES) * GSTAGE_BYTES;
        uint32_t stB = stA + 16384;
#pragma unroll
        for (int k16 = 0; k16 < 4; k16++) {
            uint32_t a[4][4], b[4][4];
#pragma unroll
            for (int mt = 0; mt < 4; mt++)
                ldsm4(a[mt], stA + arow[mt] +
                      ((((uint32_t)(k16 << 1) | (uint32_t)hiA) ^ xa) << 4));
#pragma unroll
            for (int j = 0; j < 4; j++)
                ldsm4(b[j], stB + brow[j] +
                      ((((uint32_t)(k16 << 1) | (uint32_t)khB) ^ xb) << 4));
#pragma unroll
            for (int mt = 0; mt < 4; mt++)
#pragma unroll
                for (int nt = 0; nt < 8; nt++)
                    mma_bf16(acc[mt][nt], a[mt], &b[nt >> 1][(nt & 1) * 2]);
        }
        __syncthreads();
    }

#pragma unroll
    for (int mt = 0; mt < 4; mt++) {
        int r0 = m0 + wm * 64 + mt * 16 + (lane >> 2);
#pragma unroll
        for (int nt = 0; nt < 8; nt++) {
            int cix = n0 + wn * 64 + nt * 8 + (lane & 3) * 2;
            float2 v0 = make_float2(acc[mt][nt][0], acc[mt][nt][1]);
            float2 v1 = make_float2(acc[mt][nt][2], acc[mt][nt][3]);
            size_t o0 = (size_t)r0 * N + cix;
            size_t o1 = (size_t)(r0 + 8) * N + cix;
            if (addsrc) {
                float2 a0 = *reinterpret_cast<const float2*>(addsrc + o0);
                float2 a1 = *reinterpret_cast<const float2*>(addsrc + o1);
                v0.x += a0.x; v0.y += a0.y;
                v1.x += a1.x; v1.y += a1.y;
            }
            *reinterpret_cast<float2*>(C + o0) = v0;
            *reinterpret_cast<float2*>(C + o1) = v1;
        }
    }
}

// ---------------- kNN scores via bf16 3-pass HMMA, per-CTA block-winner ----------------
// Same pipeline as gemm_bf16; epilogue = per-row max over this CTA's 128 cols.
__global__ void __launch_bounds__(128) knn_bf16_kernel(
    const __nv_bfloat16* __restrict__ Ahi, const __nv_bfloat16* __restrict__ Alo,
    const __nv_bfloat16* __restrict__ Bhi, const __nv_bfloat16* __restrict__ Blo)
{
    extern __shared__ __align__(128) char smem[];
    const uint32_t sb = smem_u32(smem);
    const int tid = threadIdx.x;
    const int lane = tid & 31, wid = tid >> 5;
    const int wm = wid & 1, wn = wid >> 1;
    const int m0 = blockIdx.y * 128, n0 = blockIdx.x * 128;
    const int K = Dx;

    const int nk = K >> 6;
    const int nch = 3 * nk;
    const __nv_bfloat16* APs[3] = {Ahi, Ahi, Alo};
    const __nv_bfloat16* BPs[3] = {Bhi, Blo, Bhi};

    float acc[4][8][4];
#pragma unroll
    for (int mt = 0; mt < 4; mt++)
#pragma unroll
        for (int nt = 0; nt < 8; nt++)
#pragma unroll
            for (int t = 0; t < 4; t++) acc[mt][nt][t] = 0.f;

    const int cblk = tid & 7, crow0 = tid >> 3;
    const uint32_t dblk = (uint32_t)((cblk ^ (crow0 & 7)) << 4);

    uint32_t arow[4], brow[4];
    const int hiA = lane >> 4;
    const int xa_base = wm * 64 + (lane & 15);
#pragma unroll
    for (int mt = 0; mt < 4; mt++) arow[mt] = (uint32_t)((xa_base + mt * 16) * 128);
    const uint32_t xa = (uint32_t)(xa_base & 7);
    const int rB0 = wn * 64 + (lane & 7) + (lane >> 4) * 8;
    const int khB = (lane >> 3) & 1;
#pragma unroll
    for (int j = 0; j < 4; j++) brow[j] = (uint32_t)((rB0 + j * 16) * 128);
    const uint32_t xb = (uint32_t)(rB0 & 7);

    auto load_chunk = [&](int c) {
        int p = c / nk, kc = c - p * nk;
        const __nv_bfloat16* Ap = APs[p] + (size_t)kc * 64 + cblk * 8;
        const __nv_bfloat16* Bp = BPs[p] + (size_t)kc * 64 + cblk * 8;
        uint32_t st = sb + (uint32_t)(c % GSTAGES) * GSTAGE_BYTES;
#pragma unroll
        for (int i = 0; i < 8; i++) {
            int row = crow0 + 16 * i;
            uint32_t d = st + (uint32_t)(row * 128) + dblk;
            cp_async16(d,         Ap + (size_t)(m0 + row) * K);
            cp_async16(d + 16384, Bp + (size_t)(n0 + row) * K);
        }
        CP_COMMIT();
    };

    load_chunk(0);
    load_chunk(1);

    for (int c = 0; c < nch; c++) {
        CP_WAIT1();
        __syncthreads();
        if (c + 2 < nch) load_chunk(c + 2); else CP_COMMIT();

        uint32_t stA = sb + (uint32_t)(c % GSTAGES) * GSTAGE_BYTES;
        uint32_t stB = stA + 16384;
#pragma unroll
        for (int k16 = 0; k16 < 4; k16++) {
            uint32_t a[4][4], b[4][4];
#pragma unroll
            for (int mt = 0; mt < 4; mt++)
                ldsm4(a[mt], stA + arow[mt] +
                      ((((uint32_t)(k16 << 1) | (uint32_t)hiA) ^ xa) << 4));
#pragma unroll
            for (int j = 0; j < 4; j++)
                ldsm4(b[j], stB + brow[j] +
                      ((((uint32_t)(k16 << 1) | (uint32_t)khB) ^ xb) << 4));
#pragma unroll
            for (int mt = 0; mt < 4; mt++)
#pragma unroll
                for (int nt = 0; nt < 8; nt++)
                    mma_bf16(acc[mt][nt], a[mt], &b[nt >> 1][(nt & 1) * 2]);
        }
        __syncthreads();
    }

    // drain all cp.async before reusing smem
    CP_WAIT0();
    __syncthreads();
    float* sv = reinterpret_cast<float*>(smem);
    int*   sc = reinterpret_cast<int*>(smem + 1024);

    // per-thread best per (mt, rowhalf): tie -> lowest col (scan ascending)
    float bv[4][2]; int bc[4][2];
#pragma unroll
    for (int mt = 0; mt < 4; mt++) { bv[mt][0] = -3.0e38f; bv[mt][1] = -3.0e38f;
                                     bc[mt][0] = 0; bc[mt][1] = 0; }
#pragma unroll
    for (int mt = 0; mt < 4; mt++)
#pragma unroll
        for (int nt = 0; nt < 8; nt++)
#pragma unroll
            for (int j = 0; j < 2; j++) {
                int col = wn * 64 + nt * 8 + (lane & 3) * 2 + j;
                float v0 = acc[mt][nt][j];
                float v1 = acc[mt][nt][2 + j];
                if (v0 > bv[mt][0]) { bv[mt][0] = v0; bc[mt][0] = col; }
                if (v1 > bv[mt][1]) { bv[mt][1] = v1; bc[mt][1] = col; }
            }
    // reduce across the quad (lanes sharing lane>>2)
#pragma unroll
    for (int off = 1; off <= 2; off <<= 1)
#pragma unroll
        for (int mt = 0; mt < 4; mt++)
#pragma unroll
            for (int h = 0; h < 2; h++) {
                float ov = __shfl_xor_sync(0xffffffffu, bv[mt][h], off);
                int oc = __shfl_xor_sync(0xffffffffu, bc[mt][h], off);
                if (ov > bv[mt][h] || (ov == bv[mt][h] && oc < bc[mt][h])) {
                    bv[mt][h] = ov; bc[mt][h] = oc;
                }
            }
    if ((lane & 3) == 0) {
#pragma unroll
        for (int mt = 0; mt < 4; mt++)
#pragma unroll
            for (int h = 0; h < 2; h++) {
                int lr = wm * 64 + mt * 16 + (lane >> 2) + h * 8;
                sv[lr * 2 + wn] = bv[mt][h];
                sc[lr * 2 + wn] = bc[mt][h];
            }
    }
    __syncthreads();
    {
        float v0 = sv[tid * 2 + 0], v1 = sv[tid * 2 + 1];
        int c0 = sc[tid * 2 + 0], c1 = sc[tid * 2 + 1];
        float v; int col;
        if (v1 > v0) { v = v1; col = c1; } else { v = v0; col = c0; }
        unsigned gb = __float_as_uint(v);
        gb = (gb & 0x80000000u) ? ~gb : (gb | 0x80000000u);
        unsigned gcol = (unsigned)(n0 + col);
        g_cand[(size_t)(m0 + tid) * (Mx/128) + blockIdx.x] =
            ((unsigned long long)gb << 32) | (unsigned)(~gcol);
    }
}

// ---------------- kNN select: exact fp32 rescore of near-best candidates ----------------
__global__ void __launch_bounds__(128) knn_select_kernel(
    const float* __restrict__ hs, const float* __restrict__ mem)
{
    const int row = blockIdx.x, tid = threadIdx.x;
    __shared__ unsigned long long swp[2];
    unsigned long long p = 0ULL;
    if (tid < 64) p = g_cand[(size_t)row * 64 + tid];
#pragma unroll
    for (int off = 16; off; off >>= 1) {
        unsigned long long o = __shfl_xor_sync(0xffffffffu, p, off);
        if (o > p) p = o;
    }
    if (tid == 0)  swp[0] = p;
    if (tid == 32) swp[1] = p;
    __syncthreads();
    unsigned long long bestp = swp[0] > swp[1] ? swp[0] : swp[1];
    float bestv = unflip_score((uint32_t)(bestp >> 32));
    float thr = bestv - 0.25f;

    __shared__ int list[64];
    __shared__ int cnt;
    if (tid == 0) cnt = 0;
    __syncthreads();
    if (tid < 64) {
        unsigned long long q = g_cand[(size_t)row * 64 + tid];
        if (unflip_score((uint32_t)(q >> 32)) >= thr) {
            int pos = atomicAdd(&cnt, 1);
            list[pos] = (int)(~(unsigned)(q & 0xffffffffu));
        }
    }
    __syncthreads();
    int n = cnt;
    const float* hrow = hs + (size_t)row * Dx;
    float bbv = -3.0e38f; int bbi = 0x7fffffff;
    __shared__ float sred[4];
    __shared__ float stot;
    for (int c = 0; c < n; c++) {
        int idx = list[c];
        const float* mrow = mem + (size_t)idx * Dx;
        float s = 0.f;
        for (int d = tid; d < Dx; d += 128) s = fmaf(hrow[d], mrow[d], s);
#pragma unroll
        for (int off = 16; off; off >>= 1) s += __shfl_xor_sync(0xffffffffu, s, off);
        if ((tid & 31) == 0) sred[tid >> 5] = s;
        __syncthreads();
        if (tid == 0) stot = sred[0] + sred[1] + sred[2] + sred[3];
        __syncthreads();
        float tot = stot;
        if (tot > bbv || (tot == bbv && idx < bbi)) { bbv = tot; bbi = idx; }
        __syncthreads();
    }
    if (tid == 0) g_nn_idx[row] = bbi;
}

// ---------------- RoPE on q,k (layout [BS, H, HD]) ----------------
__global__ void rope_kernel(const int* __restrict__ pos_ids)
{
    int i = blockIdx.x * blockDim.x + threadIdx.x;
    const int total = BSx * Hx * 64;
    if (i >= total) return;
    int d = i & 63;
    int h = (i >> 6) & (Hx - 1);
    int r = i >> 10;
    float p = (float)pos_ids[r];
    float inv = powf(10000.f, -(float)d * (1.f / 64.f));
    float a = p * inv;
    float sn, cs;
    sincosf(a, &sn, &cs);
    size_t base = ((size_t)r * Hx + h) * HDx;
    float q1 = g_q[base + d], q2 = g_q[base + d + 64];
    g_q[base + d]      = q1 * cs - q2 * sn;
    g_q[base + d + 64] = q2 * cs + q1 * sn;
    float k1 = g_k[base + d], k2 = g_k[base + d + 64];
    g_k[base + d]      = k1 * cs - k2 * sn;
    g_k[base + d + 64] = k2 * cs + k1 * sn;
}

// ---------------- flash attention (fp32, causal) ----------------
#define AT_STRIDE 132
#define AT_SMEM_FLOATS (3*64*AT_STRIDE + 64*65)
__global__ void __launch_bounds__(256) attn_kernel()
{
    extern __shared__ __align__(16) float smemf[];
    float* Qs = smemf;
    float* Ks = Qs + 64 * AT_STRIDE;
    float* Vs = Ks + 64 * AT_STRIDE;
    float* Ps = Vs + 64 * AT_STRIDE;

    const int tid = threadIdx.x;
    const int qt = blockIdx.x, h = blockIdx.y, b = blockIdx.z;
    const int q0 = qt * 64;
    const int qr = tid >> 2;
    const int j = tid & 3;
    const float scale = 0.08838834764831845f;

    {
        const float* src = g_q + (((size_t)(b * Sx + q0)) * Hx + h) * HDx;
#pragma unroll
        for (int it = 0; it < 8; it++) {
            int e = tid + it * 256;
            int row = e >> 5, c4 = e & 31;
            *reinterpret_cast<float4*>(&Qs[row * AT_STRIDE + c4 * 4]) =
                *reinterpret_cast<const float4*>(src + (size_t)row * Dx + c4 * 4);
        }
    }
    float o[32];
#pragma unroll
    for (int t = 0; t < 32; t++) o[t] = 0.f;
    float mrow = -3.0e38f, lrow = 0.f;

    for (int kt = 0; kt <= qt; kt++) {
        __syncthreads();
        const float* ksrc = g_k + (((size_t)(b * Sx + kt * 64)) * Hx + h) * HDx;
        const float* vsrc = g_v + (((size_t)(b * Sx + kt * 64)) * Hx + h) * HDx;
#pragma unroll
        for (int it = 0; it < 8; it++) {
            int e = tid + it * 256;
            int row = e >> 5, c4 = e & 31;
            *reinterpret_cast<float4*>(&Ks[row * AT_STRIDE + c4 * 4]) =
                *reinterpret_cast<const float4*>(ksrc + (size_t)row * Dx + c4 * 4);
            *reinterpret_cast<float4*>(&Vs[row * AT_STRIDE + c4 * 4]) =
                *reinterpret_cast<const float4*>(vsrc + (size_t)row * Dx + c4 * 4);
        }
        __syncthreads();

        float s[16];
#pragma unroll
        for (int kk = 0; kk < 16; kk++) s[kk] = 0.f;
        const float4* Q4 = reinterpret_cast<const float4*>(Qs + qr * AT_STRIDE);
#pragma unroll 8
        for (int d4 = 0; d4 < 32; d4++) {
            float4 qv = Q4[d4];
#pragma unroll
            for (int kk = 0; kk < 16; kk++) {
                float4 kv = *reinterpret_cast<const float4*>(
                    &Ks[(j * 16 + kk) * AT_STRIDE + d4 * 4]);
                s[kk] = fmaf(qv.x, kv.x, s[kk]);
                s[kk] = fmaf(qv.y, kv.y, s[kk]);
                s[kk] = fmaf(qv.z, kv.z, s[kk]);
                s[kk] = fmaf(qv.w, kv.w, s[kk]);
            }
        }
        const int qg = q0 + qr;
        float mloc = -3.0e38f;
#pragma unroll
        for (int kk = 0; kk < 16; kk++) {
            int kg = kt * 64 + j * 16 + kk;
            s[kk] = (kg <= qg) ? s[kk] * scale : -3.0e38f;
            mloc = fmaxf(mloc, s[kk]);
        }
        mloc = fmaxf(mloc, __shfl_xor_sync(0xffffffffu, mloc, 1));
        mloc = fmaxf(mloc, __shfl_xor_sync(0xffffffffu, mloc, 2));
        float mnew = fmaxf(mrow, mloc);
        float lloc = 0.f;
#pragma unroll
        for (int kk = 0; kk < 16; kk++) {
            float pv = expf(s[kk] - mnew);
            Ps[qr * 65 + j * 16 + kk] = pv;
            lloc += pv;
        }
        lloc += __shfl_xor_sync(0xffffffffu, lloc, 1);
        lloc += __shfl_xor_sync(0xffffffffu, lloc, 2);
        float corr = expf(mrow - mnew);
        lrow = lrow * corr + lloc;
        mrow = mnew;
#pragma unroll
        for (int t = 0; t < 32; t++) o[t] *= corr;
        __syncthreads();
        const int dbase = j * 32;
#pragma unroll 4
        for (int k = 0; k < 64; k++) {
            float pv = Ps[qr * 65 + k];
            const float4* V4 = reinterpret_cast<const float4*>(
                &Vs[k * AT_STRIDE + dbase]);
#pragma unroll
            for (int t = 0; t < 8; t++) {
                float4 vv = V4[t];
                o[t*4+0] = fmaf(pv, vv.x, o[t*4+0]);
                o[t*4+1] = fmaf(pv, vv.y, o[t*4+1]);
                o[t*4+2] = fmaf(pv, vv.z, o[t*4+2]);
                o[t*4+3] = fmaf(pv, vv.w, o[t*4+3]);
            }
        }
    }
    float invl = 1.f / lrow;
    float* dst = g_ctx + (((size_t)(b * Sx + q0 + qr)) * Hx + h) * HDx + j * 32;
#pragma unroll
    for (int t = 0; t < 8; t++) {
        float4 v;
        v.x = o[t*4+0] * invl; v.y = o[t*4+1] * invl;
        v.z = o[t*4+2] * invl; v.w = o[t*4+3] * invl;
        *reinterpret_cast<float4*>(dst + t * 4) = v;
    }
}

// ---------------- silu(gate)*up with fused hi/lo split ----------------
__global__ void silu_mul_split_kernel()
{
    int i = blockIdx.x * blockDim.x + threadIdx.x;
    float g = g_gate[i];
    float u = g_up[i];
    float v = g / (1.f + expf(-g)) * u;
    __nv_bfloat16 h = __float2bfloat16_rn(v);
    g_act_hi[i] = h;
    g_act_lo[i] = __float2bfloat16_rn(v - __bfloat162float(h));
}

// ---------------- launch ----------------
extern "C" void kernel_launch(void* const* d_in, const int* in_sizes, int n_in,
                              void* d_out, int out_size)
{
    (void)in_sizes; (void)n_in; (void)out_size;
    const float* hs        = (const float*)d_in[0];
    const int*   pos       = (const int*)  d_in[1];
    const float* mem       = (const float*)d_in[2];
    const float* gatelogit = (const float*)d_in[3];
    const float* wq        = (const float*)d_in[4];
    const float* wk        = (const float*)d_in[5];
    const float* wv        = (const float*)d_in[6];
    const float* wo        = (const float*)d_in[7];
    const float* wg        = (const float*)d_in[8];
    const float* wu        = (const float*)d_in[9];
    const float* wd        = (const float*)d_in[10];
    const float* r1        = (const float*)d_in[11];
    const float* r2        = (const float*)d_in[12];
    float* out = (float*)d_out;

    float *merged, *q, *k, *v, *ctx, *xattn, *gbuf, *ubuf;
    cudaGetSymbolAddress((void**)&merged, g_merged);
    cudaGetSymbolAddress((void**)&q,      g_q);
    cudaGetSymbolAddress((void**)&k,      g_k);
    cudaGetSymbolAddress((void**)&v,      g_v);
    cudaGetSymbolAddress((void**)&ctx,    g_ctx);
    cudaGetSymbolAddress((void**)&xattn,  g_xattn);
    cudaGetSymbolAddress((void**)&gbuf,   g_gate);
    cudaGetSymbolAddress((void**)&ubuf,   g_up);
    __nv_bfloat16 *ah, *al, *memh, *meml;
    cudaGetSymbolAddress((void**)&ah, g_act_hi);
    cudaGetSymbolAddress((void**)&al, g_act_lo);
    cudaGetSymbolAddress((void**)&memh, g_mem_hi);
    cudaGetSymbolAddress((void**)&meml, g_mem_lo);
    __nv_bfloat16 *wqh,*wql,*wkh,*wkl,*wvh,*wvl,*woh,*wol,*wgh,*wgl,*wuh,*wul,*wdh,*wdl;
    cudaGetSymbolAddress((void**)&wqh, g_wqT_hi); cudaGetSymbolAddress((void**)&wql, g_wqT_lo);
    cudaGetSymbolAddress((void**)&wkh, g_wkT_hi); cudaGetSymbolAddress((void**)&wkl, g_wkT_lo);
    cudaGetSymbolAddress((void**)&wvh, g_wvT_hi); cudaGetSymbolAddress((void**)&wvl, g_wvT_lo);
    cudaGetSymbolAddress((void**)&woh, g_woT_hi); cudaGetSymbolAddress((void**)&wol, g_woT_lo);
    cudaGetSymbolAddress((void**)&wgh, g_wgT_hi); cudaGetSymbolAddress((void**)&wgl, g_wgT_lo);
    cudaGetSymbolAddress((void**)&wuh, g_wuT_hi); cudaGetSymbolAddress((void**)&wul, g_wuT_lo);
    cudaGetSymbolAddress((void**)&wdh, g_wdT_hi); cudaGetSymbolAddress((void**)&wdl, g_wdT_lo);

    cudaFuncSetAttribute(gemm_bf16_kernel,
                         cudaFuncAttributeMaxDynamicSharedMemorySize, GS_SMEM);
    cudaFuncSetAttribute(knn_bf16_kernel,
                         cudaFuncAttributeMaxDynamicSharedMemorySize, GS_SMEM);
    const int att_smem = AT_SMEM_FLOATS * (int)sizeof(float);
    cudaFuncSetAttribute(attn_kernel,
                         cudaFuncAttributeMaxDynamicSharedMemorySize, att_smem);

    // 0. weight transpose + bf16 hi/lo split
    transpose_split_kernel<<<dim3(Dx/32, Dx/32), 256>>>(wq, wqh, wql, Dx, Dx);
    transpose_split_kernel<<<dim3(Dx/32, Dx/32), 256>>>(wk, wkh, wkl, Dx, Dx);
    transpose_split_kernel<<<dim3(Dx/32, Dx/32), 256>>>(wv, wvh, wvl, Dx, Dx);
    transpose_split_kernel<<<dim3(Dx/32, Dx/32), 256>>>(wo, woh, wol, Dx, Dx);
    transpose_split_kernel<<<dim3(Fx/32, Dx/32), 256>>>(wg, wgh, wgl, Dx, Fx);
    transpose_split_kernel<<<dim3(Fx/32, Dx/32), 256>>>(wu, wuh, wul, Dx, Fx);
    transpose_split_kernel<<<dim3(Dx/32, Fx/32), 256>>>(wd, wdh, wdl, Fx, Dx);

    // 1. kNN retrieval: bf16 3-pass HMMA block-winners + exact fp32 rescore
    split_kernel<<<(BSx*Dx)/256, 256>>>(hs, ah, al, BSx*Dx);
    split_kernel<<<(Mx*Dx)/256, 256>>>(mem, memh, meml, Mx*Dx);
    knn_bf16_kernel<<<dim3(Mx/128, BSx/128), 128, GS_SMEM>>>(ah, al, memh, meml);
    knn_select_kernel<<<BSx, 128>>>(hs, mem);

    // 2. gated L2 mix
    mix_kernel<<<BSx, 256>>>(hs, mem, gatelogit);

    // 3. RMS norm 1 -> act splits
    rmsnorm_split_kernel<<<BSx, 256>>>(merged, r1, ah, al);

    // 4. QKV projections (HMMA)
    gemm_bf16_kernel<<<dim3(Dx/128, BSx/128), 128, GS_SMEM>>>(ah, al, wqh, wql, nullptr, q, Dx, Dx);
    gemm_bf16_kernel<<<dim3(Dx/128, BSx/128), 128, GS_SMEM>>>(ah, al, wkh, wkl, nullptr, k, Dx, Dx);
    gemm_bf16_kernel<<<dim3(Dx/128, BSx/128), 128, GS_SMEM>>>(ah, al, wvh, wvl, nullptr, v, Dx, Dx);

    // 5. RoPE
    rope_kernel<<<(BSx * Hx * 64) / 256, 256>>>(pos);

    // 6. flash attention
    attn_kernel<<<dim3(Sx/64, Hx, Bx), 256, att_smem>>>();

    // 7. output projection + residual
    split_kernel<<<(BSx*Dx)/256, 256>>>(ctx, ah, al, BSx*Dx);
    gemm_bf16_kernel<<<dim3(Dx/128, BSx/128), 128, GS_SMEM>>>(ah, al, woh, wol, merged, xattn, Dx, Dx);

    // 8. RMS norm 2 -> act splits
    rmsnorm_split_kernel<<<BSx, 256>>>(xattn, r2, ah, al);

    // 9. MLP (HMMA)
    gemm_bf16_kernel<<<dim3(Fx/128, BSx/128), 128, GS_SMEM>>>(ah, al, wgh, wgl, nullptr, gbuf, Fx, Dx);
    gemm_bf16_kernel<<<dim3(Fx/128, BSx/128), 128, GS_SMEM>>>(ah, al, wuh, wul, nullptr, ubuf, Fx, Dx);
    silu_mul_split_kernel<<<(int)(((size_t)BSx*Fx)/256), 256>>>();
    gemm_bf16_kernel<<<dim3(Dx/128, BSx/128), 128, GS_SMEM>>>(ah, al, wdh, wdl, xattn, out, Dx, Fx);
}

// round 17
// speedup vs baseline: 1.2458x; 1.0547x over previous
#include <cuda_runtime.h>
#include <cuda_bf16.h>
#include <math.h>
#include <stdint.h>

// ---------------- problem constants ----------------
#define Bx 2
#define Sx 1024
#define Dx 2048
#define Hx 16
#define Fx 8192
#define Mx 8192
#define HDx 128
#define BSx (Bx*Sx)   // 2048 token rows

// ---------------- scratch ----------------
__device__ float g_merged[BSx*Dx];
__device__ float g_q[BSx*Dx];
__device__ float g_k[BSx*Dx];
__device__ float g_v[BSx*Dx];
__device__ float g_xattn[BSx*Dx];
__device__ float g_gate[(size_t)BSx*Fx];
__device__ float g_up[(size_t)BSx*Fx];
__device__ int g_nn_idx[BSx];
__device__ unsigned long long g_cand[(size_t)BSx * 128];   // 64 blocks x top-2

// bf16 hi/lo splits
__device__ __align__(256) __nv_bfloat16 g_act_hi[(size_t)BSx*Fx];
__device__ __align__(256) __nv_bfloat16 g_act_lo[(size_t)BSx*Fx];
__device__ __align__(256) __nv_bfloat16 g_mem_hi[(size_t)Mx*Dx];
__device__ __align__(256) __nv_bfloat16 g_wqT_hi[Dx*Dx];
__device__ __align__(256) __nv_bfloat16 g_wqT_lo[Dx*Dx];
__device__ __align__(256) __nv_bfloat16 g_wkT_hi[Dx*Dx];
__device__ __align__(256) __nv_bfloat16 g_wkT_lo[Dx*Dx];
__device__ __align__(256) __nv_bfloat16 g_wvT_hi[Dx*Dx];
__device__ __align__(256) __nv_bfloat16 g_wvT_lo[Dx*Dx];
__device__ __align__(256) __nv_bfloat16 g_woT_hi[Dx*Dx];
__device__ __align__(256) __nv_bfloat16 g_woT_lo[Dx*Dx];
__device__ __align__(256) __nv_bfloat16 g_wgT_hi[(size_t)Fx*Dx];
__device__ __align__(256) __nv_bfloat16 g_wgT_lo[(size_t)Fx*Dx];
__device__ __align__(256) __nv_bfloat16 g_wuT_hi[(size_t)Fx*Dx];
__device__ __align__(256) __nv_bfloat16 g_wuT_lo[(size_t)Fx*Dx];
__device__ __align__(256) __nv_bfloat16 g_wdT_hi[(size_t)Dx*Fx];
__device__ __align__(256) __nv_bfloat16 g_wdT_lo[(size_t)Dx*Fx];

// ---------------- PTX helpers (baseline sm_80+ only) ----------------
__device__ __forceinline__ uint32_t smem_u32(const void* p) {
    uint32_t a;
    asm("{ .reg .u64 t; cvta.to.shared.u64 t, %1; cvt.u32.u64 %0, t; }"
        : "=r"(a) : "l"(p));
    return a;
}
__device__ __forceinline__ void cp_async16(uint32_t dst, const void* src) {
    asm volatile("cp.async.cg.shared.global [%0], [%1], 16;"
                 :: "r"(dst), "l"(src) : "memory");
}
#define CP_COMMIT() asm volatile("cp.async.commit_group;" ::: "memory")
#define CP_WAIT1()  asm volatile("cp.async.wait_group 1;" ::: "memory")
#define CP_WAIT0()  asm volatile("cp.async.wait_group 0;" ::: "memory")

__device__ __forceinline__ void ldsm4(uint32_t* r, uint32_t addr) {
    asm volatile("ldmatrix.sync.aligned.m8n8.x4.shared.b16 {%0,%1,%2,%3}, [%4];"
                 : "=r"(r[0]), "=r"(r[1]), "=r"(r[2]), "=r"(r[3]) : "r"(addr));
}
__device__ __forceinline__ void mma_bf16(float* c, const uint32_t* a, const uint32_t* b) {
    asm volatile(
        "mma.sync.aligned.m16n8k16.row.col.f32.bf16.bf16.f32 "
        "{%0,%1,%2,%3}, {%4,%5,%6,%7}, {%8,%9}, {%0,%1,%2,%3};"
        : "+f"(c[0]), "+f"(c[1]), "+f"(c[2]), "+f"(c[3])
        : "r"(a[0]), "r"(a[1]), "r"(a[2]), "r"(a[3]), "r"(b[0]), "r"(b[1]));
}
__device__ __forceinline__ float unflip_score(uint32_t u) {
    return __uint_as_float((u & 0x80000000u) ? (u ^ 0x80000000u) : ~u);
}
__device__ __forceinline__ unsigned long long pack_score(float v, int col) {
    unsigned gb = __float_as_uint(v);
    gb = (gb & 0x80000000u) ? ~gb : (gb | 0x80000000u);
    return ((unsigned long long)gb << 32) | (unsigned)(~(unsigned)col);
}

// ---------------- gated L2-normalized mix ----------------
__global__ void __launch_bounds__(256) mix_kernel(
    const float* __restrict__ hs, const float* __restrict__ mem,
    const float* __restrict__ gate_logit)
{
    int r = blockIdx.x;
    const float* hrow = hs + (size_t)r * Dx;
    int idx = g_nn_idx[r];
    const float* mrow = mem + (size_t)idx * Dx;

    float sh = 0.f, sm = 0.f;
    for (int d = threadIdx.x; d < Dx; d += 256) {
        float a = hrow[d]; sh += a * a;
        float c = mrow[d]; sm += c * c;
    }
#pragma unroll
    for (int off = 16; off; off >>= 1) {
        sh += __shfl_xor_sync(0xffffffffu, sh, off);
        sm += __shfl_xor_sync(0xffffffffu, sm, off);
    }
    __shared__ float redh[8], redm[8];
    __shared__ float s_ratio;
    int lane = threadIdx.x & 31, wp = threadIdx.x >> 5;
    if (lane == 0) { redh[wp] = sh; redm[wp] = sm; }
    __syncthreads();
    if (threadIdx.x == 0) {
        float th = 0.f, tm = 0.f;
        for (int i = 0; i < 8; i++) { th += redh[i]; tm += redm[i]; }
        float nh = sqrtf(th) + 1e-4f;
        float nm = sqrtf(tm) + 1e-4f;
        s_ratio = nh / nm;
    }
    __syncthreads();
    float ratio = s_ratio;
    for (int d = threadIdx.x; d < Dx; d += 256) {
        float g = 1.f / (1.f + expf(-gate_logit[d]));
        g_merged[(size_t)r * Dx + d] = g * hrow[d] + (1.f - g) * mrow[d] * ratio;
    }
}

// ---------------- RMS norm with fused bf16 hi/lo split output ----------------
__global__ void __launch_bounds__(256) rmsnorm_split_kernel(
    const float* __restrict__ x, const float* __restrict__ w,
    __nv_bfloat16* __restrict__ hi, __nv_bfloat16* __restrict__ lo)
{
    int r = blockIdx.x;
    const float* row = x + (size_t)r * Dx;
    float ss = 0.f;
    for (int d = threadIdx.x; d < Dx; d += 256) { float a = row[d]; ss += a * a; }
#pragma unroll
    for (int off = 16; off; off >>= 1) ss += __shfl_xor_sync(0xffffffffu, ss, off);
    __shared__ float red[8];
    __shared__ float s_scale;
    int lane = threadIdx.x & 31, wp = threadIdx.x >> 5;
    if (lane == 0) red[wp] = ss;
    __syncthreads();
    if (threadIdx.x == 0) {
        float t = 0.f;
        for (int i = 0; i < 8; i++) t += red[i];
        s_scale = rsqrtf(t / (float)Dx + 1e-6f);
    }
    __syncthreads();
    float sc = s_scale;
    for (int d = threadIdx.x; d < Dx; d += 256) {
        float v = row[d] * sc * w[d];
        __nv_bfloat16 h = __float2bfloat16_rn(v);
        size_t o = (size_t)r * Dx + d;
        hi[o] = h;
        lo[o] = __float2bfloat16_rn(v - __bfloat162float(h));
    }
}

// ---------------- hi-only bf16 split ----------------
__global__ void split_hi_kernel(const float* __restrict__ x,
                                __nv_bfloat16* __restrict__ hi, int n)
{
    int i = blockIdx.x * blockDim.x + threadIdx.x;
    if (i < n) hi[i] = __float2bfloat16_rn(x[i]);
}

// ---------------- transpose + split: W[K,N] -> T[N,K] hi/lo ----------------
__global__ void __launch_bounds__(256) transpose_split_kernel(
    const float* __restrict__ W, __nv_bfloat16* __restrict__ hiT,
    __nv_bfloat16* __restrict__ loT, int K, int N)
{
    __shared__ float tile[32][33];
    int n0 = blockIdx.x * 32, k0 = blockIdx.y * 32;
    int tx = threadIdx.x & 31, ty = threadIdx.x >> 5;  // 32x8
#pragma unroll
    for (int i = 0; i < 4; i++)
        tile[ty + i*8][tx] = W[(size_t)(k0 + ty + i*8) * N + n0 + tx];
    __syncthreads();
#pragma unroll
    for (int i = 0; i < 4; i++) {
        float v = tile[tx][ty + i*8];
        __nv_bfloat16 h = __float2bfloat16_rn(v);
        size_t o = (size_t)(n0 + ty + i*8) * K + k0 + tx;
        hiT[o] = h;
        loT[o] = __float2bfloat16_rn(v - __bfloat162float(h));
    }
}

// ---------------- HMMA bf16 3-pass GEMM (mma.sync, baseline PTX) ----------------
#define GSTAGES 3
#define GSTAGE_BYTES 32768              // A 16KB + B 16KB (SW128 swizzled)
#define GS_SMEM (GSTAGES * GSTAGE_BYTES)
__global__ void __launch_bounds__(128) gemm_bf16_kernel(
    const __nv_bfloat16* __restrict__ Ahi, const __nv_bfloat16* __restrict__ Alo,
    const __nv_bfloat16* __restrict__ Bhi, const __nv_bfloat16* __restrict__ Blo,
    const float* __restrict__ addsrc, float* __restrict__ C, int N, int K)
{
    extern __shared__ __align__(128) char smem[];
    const uint32_t sb = smem_u32(smem);
    const int tid = threadIdx.x;
    const int lane = tid & 31, wid = tid >> 5;
    const int wm = wid & 1, wn = wid >> 1;
    const int m0 = blockIdx.y * 128, n0 = blockIdx.x * 128;

    const int nk = K >> 6;
    const int nch = 3 * nk;
    const __nv_bfloat16* APs[3] = {Ahi, Ahi, Alo};
    const __nv_bfloat16* BPs[3] = {Bhi, Blo, Bhi};

    float acc[4][8][4];
#pragma unroll
    for (int mt = 0; mt < 4; mt++)
#pragma unroll
        for (int nt = 0; nt < 8; nt++)
#pragma unroll
            for (int t = 0; t < 4; t++) acc[mt][nt][t] = 0.f;

    const int cblk = tid & 7, crow0 = tid >> 3;
    const uint32_t dblk = (uint32_t)((cblk ^ (crow0 & 7)) << 4);

    uint32_t arow[4], brow[4];
    const int hiA = lane >> 4;
    const int xa_base = wm * 64 + (lane & 15);
#pragma unroll
    for (int mt = 0; mt < 4; mt++) arow[mt] = (uint32_t)((xa_base + mt * 16) * 128);
    const uint32_t xa = (uint32_t)(xa_base & 7);
    const int rB0 = wn * 64 + (lane & 7) + (lane >> 4) * 8;
    const int khB = (lane >> 3) & 1;
#pragma unroll
    for (int j = 0; j < 4; j++) brow[j] = (uint32_t)((rB0 + j * 16) * 128);
    const uint32_t xb = (uint32_t)(rB0 & 7);

    auto load_chunk = [&](int c) {
        int p = c / nk, kc = c - p * nk;
        const __nv_bfloat16* Ap = APs[p] + (size_t)kc * 64 + cblk * 8;
        const __nv_bfloat16* Bp = BPs[p] + (size_t)kc * 64 + cblk * 8;
        uint32_t st = sb + (uint32_t)(c % GSTAGES) * GSTAGE_BYTES;
#pragma unroll
        for (int i = 0; i < 8; i++) {
            int row = crow0 + 16 * i;
            uint32_t d = st + (uint32_t)(row * 128) + dblk;
            cp_async16(d,         Ap + (size_t)(m0 + row) * K);
            cp_async16(d + 16384, Bp + (size_t)(n0 + row) * K);
        }
        CP_COMMIT();
    };

    load_chunk(0);
    load_chunk(1);

    for (int c = 0; c < nch; c++) {
        CP_WAIT1();
        __syncthreads();
        if (c + 2 < nch) load_chunk(c + 2); else CP_COMMIT();

        uint32_t stA = sb + (uint32_t)(c % GSTAGES) * GSTAGE_BYTES;
        uint32_t stB = stA + 16384;
#pragma unroll
        for (int k16 = 0; k16 < 4; k16++) {
            uint32_t a[4][4], b[4][4];
#pragma unroll
            for (int mt = 0; mt < 4; mt++)
                ldsm4(a[mt], stA + arow[mt] +
                      ((((uint32_t)(k16 << 1) | (uint32_t)hiA) ^ xa) << 4));
#pragma unroll
            for (int j = 0; j < 4; j++)
                ldsm4(b[j], stB + brow[j] +
                      ((((uint32_t)(k16 << 1) | (uint32_t)khB) ^ xb) << 4));
#pragma unroll
            for (int mt = 0; mt < 4; mt++)
#pragma unroll
                for (int nt = 0; nt < 8; nt++)
                    mma_bf16(acc[mt][nt], a[mt], &b[nt >> 1][(nt & 1) * 2]);
        }
        __syncthreads();
    }

#pragma unroll
    for (int mt = 0; mt < 4; mt++) {
        int r0 = m0 + wm * 64 + mt * 16 + (lane >> 2);
#pragma unroll
        for (int nt = 0; nt < 8; nt++) {
            int cix = n0 + wn * 64 + nt * 8 + (lane & 3) * 2;
            float2 v0 = make_float2(acc[mt][nt][0], acc[mt][nt][1]);
            float2 v1 = make_float2(acc[mt][nt][2], acc[mt][nt][3]);
            size_t o0 = (size_t)r0 * N + cix;
            size_t o1 = (size_t)(r0 + 8) * N + cix;
            if (addsrc) {
                float2 a0 = *reinterpret_cast<const float2*>(addsrc + o0);
                float2 a1 = *reinterpret_cast<const float2*>(addsrc + o1);
                v0.x += a0.x; v0.y += a0.y;
                v1.x += a1.x; v1.y += a1.y;
            }
            *reinterpret_cast<float2*>(C + o0) = v0;
            *reinterpret_cast<float2*>(C + o1) = v1;
        }
    }
}

// ---------------- kNN scores: single-pass bf16 HMMA, top-2 per 128-col block ----------------
__global__ void __launch_bounds__(128) knn_bf16_kernel(
    const __nv_bfloat16* __restrict__ Ahi, const __nv_bfloat16* __restrict__ Bhi)
{
    extern __shared__ __align__(128) char smem[];
    const uint32_t sb = smem_u32(smem);
    const int tid = threadIdx.x;
    const int lane = tid & 31, wid = tid >> 5;
    const int wm = wid & 1, wn = wid >> 1;
    const int m0 = blockIdx.y * 128, n0 = blockIdx.x * 128;
    const int K = Dx;
    const int nch = K >> 6;

    float acc[4][8][4];
#pragma unroll
    for (int mt = 0; mt < 4; mt++)
#pragma unroll
        for (int nt = 0; nt < 8; nt++)
#pragma unroll
            for (int t = 0; t < 4; t++) acc[mt][nt][t] = 0.f;

    const int cblk = tid & 7, crow0 = tid >> 3;
    const uint32_t dblk = (uint32_t)((cblk ^ (crow0 & 7)) << 4);

    uint32_t arow[4], brow[4];
    const int hiA = lane >> 4;
    const int xa_base = wm * 64 + (lane & 15);
#pragma unroll
    for (int mt = 0; mt < 4; mt++) arow[mt] = (uint32_t)((xa_base + mt * 16) * 128);
    const uint32_t xa = (uint32_t)(xa_base & 7);
    const int rB0 = wn * 64 + (lane & 7) + (lane >> 4) * 8;
    const int khB = (lane >> 3) & 1;
#pragma unroll
    for (int j = 0; j < 4; j++) brow[j] = (uint32_t)((rB0 + j * 16) * 128);
    const uint32_t xb = (uint32_t)(rB0 & 7);

    auto load_chunk = [&](int c) {
        const __nv_bfloat16* Ap = Ahi + (size_t)c * 64 + cblk * 8;
        const __nv_bfloat16* Bp = Bhi + (size_t)c * 64 + cblk * 8;
        uint32_t st = sb + (uint32_t)(c % GSTAGES) * GSTAGE_BYTES;
#pragma unroll
        for (int i = 0; i < 8; i++) {
            int row = crow0 + 16 * i;
            uint32_t d = st + (uint32_t)(row * 128) + dblk;
            cp_async16(d,         Ap + (size_t)(m0 + row) * K);
            cp_async16(d + 16384, Bp + (size_t)(n0 + row) * K);
        }
        CP_COMMIT();
    };

    load_chunk(0);
    load_chunk(1);

    for (int c = 0; c < nch; c++) {
        CP_WAIT1();
        __syncthreads();
        if (c + 2 < nch) load_chunk(c + 2); else CP_COMMIT();

        uint32_t stA = sb + (uint32_t)(c % GSTAGES) * GSTAGE_BYTES;
        uint32_t stB = stA + 16384;
#pragma unroll
        for (int k16 = 0; k16 < 4; k16++) {
            uint32_t a[4][4], b[4][4];
#pragma unroll
            for (int mt = 0; mt < 4; mt++)
                ldsm4(a[mt], stA + arow[mt] +
                      ((((uint32_t)(k16 << 1) | (uint32_t)hiA) ^ xa) << 4));
#pragma unroll
            for (int j = 0; j < 4; j++)
                ldsm4(b[j], stB + brow[j] +
                      ((((uint32_t)(k16 << 1) | (uint32_t)khB) ^ xb) << 4));
#pragma unroll
            for (int mt = 0; mt < 4; mt++)
#pragma unroll
                for (int nt = 0; nt < 8; nt++)
                    mma_bf16(acc[mt][nt], a[mt], &b[nt >> 1][(nt & 1) * 2]);
        }
        __syncthreads();
    }

    // drain cp.async before reusing smem for the reduction
    CP_WAIT0();
    __syncthreads();
    float* sv = reinterpret_cast<float*>(smem);   // [128 rows][2 wn][4: v1,c1,v2,c2]

    // per-thread top-2 over its 16 cols, per (mt, rowhalf)
    float v1[4][2], v2[4][2]; int c1[4][2], c2[4][2];
#pragma unroll
    for (int mt = 0; mt < 4; mt++)
#pragma unroll
        for (int h = 0; h < 2; h++) {
            v1[mt][h] = -3.0e38f; v2[mt][h] = -3.0e38f;
            c1[mt][h] = 0; c2[mt][h] = 0;
        }
#pragma unroll
    for (int mt = 0; mt < 4; mt++)
#pragma unroll
        for (int nt = 0; nt < 8; nt++)
#pragma unroll
            for (int h = 0; h < 2; h++)
#pragma unroll
                for (int j = 0; j < 2; j++) {
                    int col = wn * 64 + nt * 8 + (lane & 3) * 2 + j;
                    float val = acc[mt][nt][h * 2 + j];
                    if (val > v1[mt][h]) {
                        v2[mt][h] = v1[mt][h]; c2[mt][h] = c1[mt][h];
                        v1[mt][h] = val; c1[mt][h] = col;
                    } else if (val > v2[mt][h]) {
                        v2[mt][h] = val; c2[mt][h] = col;
                    }
                }
    // quad reduce (lanes sharing lane>>2), merging top-2 pairs
#pragma unroll
    for (int off = 1; off <= 2; off <<= 1)
#pragma unroll
        for (int mt = 0; mt < 4; mt++)
#pragma unroll
            for (int h = 0; h < 2; h++) {
                float ov1 = __shfl_xor_sync(0xffffffffu, v1[mt][h], off);
                int   oc1 = __shfl_xor_sync(0xffffffffu, c1[mt][h], off);
                float ov2 = __shfl_xor_sync(0xffffffffu, v2[mt][h], off);
                int   oc2 = __shfl_xor_sync(0xffffffffu, c2[mt][h], off);
                if (ov1 > v1[mt][h]) {
                    v2[mt][h] = v1[mt][h]; c2[mt][h] = c1[mt][h];
                    v1[mt][h] = ov1; c1[mt][h] = oc1;
                    if (ov2 > v2[mt][h]) { v2[mt][h] = ov2; c2[mt][h] = oc2; }
                } else if (ov1 > v2[mt][h]) {
                    v2[mt][h] = ov1; c2[mt][h] = oc1;
                }
            }
    if ((lane & 3) == 0) {
#pragma unroll
        for (int mt = 0; mt < 4; mt++)
#pragma unroll
            for (int h = 0; h < 2; h++) {
                int lr = wm * 64 + mt * 16 + (lane >> 2) + h * 8;
                float* e = sv + (size_t)(lr * 2 + wn) * 4;
                e[0] = v1[mt][h]; e[1] = __int_as_float(c1[mt][h]);
                e[2] = v2[mt][h]; e[3] = __int_as_float(c2[mt][h]);
            }
    }
    __syncthreads();
    {
        const float* e0 = sv + (size_t)(tid * 2 + 0) * 4;
        const float* e1 = sv + (size_t)(tid * 2 + 1) * 4;
        float a1 = e0[0], a2 = e0[2], b1 = e1[0], b2 = e1[2];
        int   A1 = __float_as_int(e0[1]), A2 = __float_as_int(e0[3]);
        int   B1 = __float_as_int(e1[1]), B2 = __float_as_int(e1[3]);
        float t1, t2; int T1, T2;
        if (a1 >= b1) {
            t1 = a1; T1 = A1;
            if (b1 >= a2) { t2 = b1; T2 = B1; }
            else          { t2 = a2; T2 = A2; }
        } else {
            t1 = b1; T1 = B1;
            if (a1 >= b2) { t2 = a1; T2 = A1; }
            else          { t2 = b2; T2 = B2; }
        }
        size_t base = ((size_t)(m0 + tid) * 64 + blockIdx.x) * 2;
        g_cand[base + 0] = pack_score(t1, n0 + T1);
        g_cand[base + 1] = pack_score(t2, n0 + T2);
    }
}

// ---------------- kNN select: exact fp32 rescore of near-best candidates ----------------
__global__ void __launch_bounds__(128) knn_select_kernel(
    const float* __restrict__ hs, const float* __restrict__ mem)
{
    const int row = blockIdx.x, tid = threadIdx.x;
    __shared__ unsigned long long swp[4];
    unsigned long long p = g_cand[(size_t)row * 128 + tid];
    unsigned long long w = p;
#pragma unroll
    for (int off = 16; off; off >>= 1) {
        unsigned long long o = __shfl_xor_sync(0xffffffffu, w, off);
        if (o > w) w = o;
    }
    if ((tid & 31) == 0) swp[tid >> 5] = w;
    __syncthreads();
    unsigned long long bestp = swp[0];
    if (swp[1] > bestp) bestp = swp[1];
    if (swp[2] > bestp) bestp = swp[2];
    if (swp[3] > bestp) bestp = swp[3];
    float bestv = unflip_score((uint32_t)(bestp >> 32));
    float thr = bestv - 1.25f;

    __shared__ int list[128];
    __shared__ int cnt;
    if (tid == 0) cnt = 0;
    __syncthreads();
    if (unflip_score((uint32_t)(p >> 32)) >= thr) {
        int pos = atomicAdd(&cnt, 1);
        list[pos] = (int)(~(unsigned)(p & 0xffffffffu));
    }
    __syncthreads();
    int n = cnt;
    const float* hrow = hs + (size_t)row * Dx;
    float bbv = -3.0e38f; int bbi = 0x7fffffff;
    __shared__ float sred[4];
    __shared__ float stot;
    for (int c = 0; c < n; c++) {
        int idx = list[c];
        const float* mrow = mem + (size_t)idx * Dx;
        float s = 0.f;
        for (int d = tid; d < Dx; d += 128) s = fmaf(hrow[d], mrow[d], s);
#pragma unroll
        for (int off = 16; off; off >>= 1) s += __shfl_xor_sync(0xffffffffu, s, off);
        if ((tid & 31) == 0) sred[tid >> 5] = s;
        __syncthreads();
        if (tid == 0) stot = sred[0] + sred[1] + sred[2] + sred[3];
        __syncthreads();
        float tot = stot;
        if (tot > bbv || (tot == bbv && idx < bbi)) { bbv = tot; bbi = idx; }
        __syncthreads();
    }
    if (tid == 0) g_nn_idx[row] = bbi;
}

// ---------------- RoPE on q,k (layout [BS, H, HD]) ----------------
__global__ void rope_kernel(const int* __restrict__ pos_ids)
{
    int i = blockIdx.x * blockDim.x + threadIdx.x;
    const int total = BSx * Hx * 64;
    if (i >= total) return;
    int d = i & 63;
    int h = (i >> 6) & (Hx - 1);
    int r = i >> 10;
    float p = (float)pos_ids[r];
    float inv = powf(10000.f, -(float)d * (1.f / 64.f));
    float a = p * inv;
    float sn, cs;
    sincosf(a, &sn, &cs);
    size_t base = ((size_t)r * Hx + h) * HDx;
    float q1 = g_q[base + d], q2 = g_q[base + d + 64];
    g_q[base + d]      = q1 * cs - q2 * sn;
    g_q[base + d + 64] = q2 * cs + q1 * sn;
    float k1 = g_k[base + d], k2 = g_k[base + d + 64];
    g_k[base + d]      = k1 * cs - k2 * sn;
    g_k[base + d + 64] = k2 * cs + k1 * sn;
}

// ---------------- flash attention (fp32, causal); epilogue writes ctx hi/lo split ----------------
#define AT_STRIDE 132
#define AT_SMEM_FLOATS (3*64*AT_STRIDE + 64*65)
__global__ void __launch_bounds__(256) attn_kernel()
{
    extern __shared__ __align__(16) float smemf[];
    float* Qs = smemf;
    float* Ks = Qs + 64 * AT_STRIDE;
    float* Vs = Ks + 64 * AT_STRIDE;
    float* Ps = Vs + 64 * AT_STRIDE;

    const int tid = threadIdx.x;
    const int qt = blockIdx.x, h = blockIdx.y, b = blockIdx.z;
    const int q0 = qt * 64;
    const int qr = tid >> 2;
    const int j = tid & 3;
    const float scale = 0.08838834764831845f;

    {
        const float* src = g_q + (((size_t)(b * Sx + q0)) * Hx + h) * HDx;
#pragma unroll
        for (int it = 0; it < 8; it++) {
            int e = tid + it * 256;
            int row = e >> 5, c4 = e & 31;
            *reinterpret_cast<float4*>(&Qs[row * AT_STRIDE + c4 * 4]) =
                *reinterpret_cast<const float4*>(src + (size_t)row * Dx + c4 * 4);
        }
    }
    float o[32];
#pragma unroll
    for (int t = 0; t < 32; t++) o[t] = 0.f;
    float mrow = -3.0e38f, lrow = 0.f;

    for (int kt = 0; kt <= qt; kt++) {
        __syncthreads();
        const float* ksrc = g_k + (((size_t)(b * Sx + kt * 64)) * Hx + h) * HDx;
        const float* vsrc = g_v + (((size_t)(b * Sx + kt * 64)) * Hx + h) * HDx;
#pragma unroll
        for (int it = 0; it < 8; it++) {
            int e = tid + it * 256;
            int row = e >> 5, c4 = e & 31;
            *reinterpret_cast<float4*>(&Ks[row * AT_STRIDE + c4 * 4]) =
                *reinterpret_cast<const float4*>(ksrc + (size_t)row * Dx + c4 * 4);
            *reinterpret_cast<float4*>(&Vs[row * AT_STRIDE + c4 * 4]) =
                *reinterpret_cast<const float4*>(vsrc + (size_t)row * Dx + c4 * 4);
        }
        __syncthreads();

        float s[16];
#pragma unroll
        for (int kk = 0; kk < 16; kk++) s[kk] = 0.f;
        const float4* Q4 = reinterpret_cast<const float4*>(Qs + qr * AT_STRIDE);
#pragma unroll 8
        for (int d4 = 0; d4 < 32; d4++) {
            float4 qv = Q4[d4];
#pragma unroll
            for (int kk = 0; kk < 16; kk++) {
                float4 kv = *reinterpret_cast<const float4*>(
                    &Ks[(j * 16 + kk) * AT_STRIDE + d4 * 4]);
                s[kk] = fmaf(qv.x, kv.x, s[kk]);
                s[kk] = fmaf(qv.y, kv.y, s[kk]);
                s[kk] = fmaf(qv.z, kv.z, s[kk]);
                s[kk] = fmaf(qv.w, kv.w, s[kk]);
            }
        }
        const int qg = q0 + qr;
        float mloc = -3.0e38f;
#pragma unroll
        for (int kk = 0; kk < 16; kk++) {
            int kg = kt * 64 + j * 16 + kk;
            s[kk] = (kg <= qg) ? s[kk] * scale : -3.0e38f;
            mloc = fmaxf(mloc, s[kk]);
        }
        mloc = fmaxf(mloc, __shfl_xor_sync(0xffffffffu, mloc, 1));
        mloc = fmaxf(mloc, __shfl_xor_sync(0xffffffffu, mloc, 2));
        float mnew = fmaxf(mrow, mloc);
        float lloc = 0.f;
#pragma unroll
        for (int kk = 0; kk < 16; kk++) {
            float pv = expf(s[kk] - mnew);
            Ps[qr * 65 + j * 16 + kk] = pv;
            lloc += pv;
        }
        lloc += __shfl_xor_sync(0xffffffffu, lloc, 1);
        lloc += __shfl_xor_sync(0xffffffffu, lloc, 2);
        float corr = expf(mrow - mnew);
        lrow = lrow * corr + lloc;
        mrow = mnew;
#pragma unroll
        for (int t = 0; t < 32; t++) o[t] *= corr;
        __syncthreads();
        const int dbase = j * 32;
#pragma unroll 4
        for (int k = 0; k < 64; k++) {
            float pv = Ps[qr * 65 + k];
            const float4* V4 = reinterpret_cast<const float4*>(
                &Vs[k * AT_STRIDE + dbase]);
#pragma unroll
            for (int t = 0; t < 8; t++) {
                float4 vv = V4[t];
                o[t*4+0] = fmaf(pv, vv.x, o[t*4+0]);
                o[t*4+1] = fmaf(pv, vv.y, o[t*4+1]);
                o[t*4+2] = fmaf(pv, vv.z, o[t*4+2]);
                o[t*4+3] = fmaf(pv, vv.w, o[t*4+3]);
            }
        }
    }
    float invl = 1.f / lrow;
    size_t base = (((size_t)(b * Sx + q0 + qr)) * Hx + h) * HDx + j * 32;
#pragma unroll
    for (int t = 0; t < 16; t++) {
        float f0 = o[t*2+0] * invl;
        float f1 = o[t*2+1] * invl;
        __nv_bfloat16 h0 = __float2bfloat16_rn(f0);
        __nv_bfloat16 h1 = __float2bfloat16_rn(f1);
        __nv_bfloat162 hp; hp.x = h0; hp.y = h1;
        __nv_bfloat162 lp;
        lp.x = __float2bfloat16_rn(f0 - __bfloat162float(h0));
        lp.y = __float2bfloat16_rn(f1 - __bfloat162float(h1));
        *reinterpret_cast<__nv_bfloat162*>(g_act_hi + base + t * 2) = hp;
        *reinterpret_cast<__nv_bfloat162*>(g_act_lo + base + t * 2) = lp;
    }
}

// ---------------- silu(gate)*up with fused hi/lo split ----------------
__global__ void silu_mul_split_kernel()
{
    int i = blockIdx.x * blockDim.x + threadIdx.x;
    float g = g_gate[i];
    float u = g_up[i];
    float v = g / (1.f + expf(-g)) * u;
    __nv_bfloat16 h = __float2bfloat16_rn(v);
    g_act_hi[i] = h;
    g_act_lo[i] = __float2bfloat16_rn(v - __bfloat162float(h));
}

// ---------------- launch ----------------
extern "C" void kernel_launch(void* const* d_in, const int* in_sizes, int n_in,
                              void* d_out, int out_size)
{
    (void)in_sizes; (void)n_in; (void)out_size;
    const float* hs        = (const float*)d_in[0];
    const int*   pos       = (const int*)  d_in[1];
    const float* mem       = (const float*)d_in[2];
    const float* gatelogit = (const float*)d_in[3];
    const float* wq        = (const float*)d_in[4];
    const float* wk        = (const float*)d_in[5];
    const float* wv        = (const float*)d_in[6];
    const float* wo        = (const float*)d_in[7];
    const float* wg        = (const float*)d_in[8];
    const float* wu        = (const float*)d_in[9];
    const float* wd        = (const float*)d_in[10];
    const float* r1        = (const float*)d_in[11];
    const float* r2        = (const float*)d_in[12];
    float* out = (float*)d_out;

    float *merged, *q, *k, *v, *xattn, *gbuf, *ubuf;
    cudaGetSymbolAddress((void**)&merged, g_merged);
    cudaGetSymbolAddress((void**)&q,      g_q);
    cudaGetSymbolAddress((void**)&k,      g_k);
    cudaGetSymbolAddress((void**)&v,      g_v);
    cudaGetSymbolAddress((void**)&xattn,  g_xattn);
    cudaGetSymbolAddress((void**)&gbuf,   g_gate);
    cudaGetSymbolAddress((void**)&ubuf,   g_up);
    __nv_bfloat16 *ah, *al, *memh;
    cudaGetSymbolAddress((void**)&ah, g_act_hi);
    cudaGetSymbolAddress((void**)&al, g_act_lo);
    cudaGetSymbolAddress((void**)&memh, g_mem_hi);
    __nv_bfloat16 *wqh,*wql,*wkh,*wkl,*wvh,*wvl,*woh,*wol,*wgh,*wgl,*wuh,*wul,*wdh,*wdl;
    cudaGetSymbolAddress((void**)&wqh, g_wqT_hi); cudaGetSymbolAddress((void**)&wql, g_wqT_lo);
    cudaGetSymbolAddress((void**)&wkh, g_wkT_hi); cudaGetSymbolAddress((void**)&wkl, g_wkT_lo);
    cudaGetSymbolAddress((void**)&wvh, g_wvT_hi); cudaGetSymbolAddress((void**)&wvl, g_wvT_lo);
    cudaGetSymbolAddress((void**)&woh, g_woT_hi); cudaGetSymbolAddress((void**)&wol, g_woT_lo);
    cudaGetSymbolAddress((void**)&wgh, g_wgT_hi); cudaGetSymbolAddress((void**)&wgl, g_wgT_lo);
    cudaGetSymbolAddress((void**)&wuh, g_wuT_hi); cudaGetSymbolAddress((void**)&wul, g_wuT_lo);
    cudaGetSymbolAddress((void**)&wdh, g_wdT_hi); cudaGetSymbolAddress((void**)&wdl, g_wdT_lo);

    cudaFuncSetAttribute(gemm_bf16_kernel,
                         cudaFuncAttributeMaxDynamicSharedMemorySize, GS_SMEM);
    cudaFuncSetAttribute(knn_bf16_kernel,
                         cudaFuncAttributeMaxDynamicSharedMemorySize, GS_SMEM);
    const int att_smem = AT_SMEM_FLOATS * (int)sizeof(float);
    cudaFuncSetAttribute(attn_kernel,
                         cudaFuncAttributeMaxDynamicSharedMemorySize, att_smem);

    // 0. weight transpose + bf16 hi/lo split
    transpose_split_kernel<<<dim3(Dx/32, Dx/32), 256>>>(wq, wqh, wql, Dx, Dx);
    transpose_split_kernel<<<dim3(Dx/32, Dx/32), 256>>>(wk, wkh, wkl, Dx, Dx);
    transpose_split_kernel<<<dim3(Dx/32, Dx/32), 256>>>(wv, wvh, wvl, Dx, Dx);
    transpose_split_kernel<<<dim3(Dx/32, Dx/32), 256>>>(wo, woh, wol, Dx, Dx);
    transpose_split_kernel<<<dim3(Fx/32, Dx/32), 256>>>(wg, wgh, wgl, Dx, Fx);
    transpose_split_kernel<<<dim3(Fx/32, Dx/32), 256>>>(wu, wuh, wul, Dx, Fx);
    transpose_split_kernel<<<dim3(Dx/32, Fx/32), 256>>>(wd, wdh, wdl, Fx, Dx);

    // 1. kNN retrieval: 1-pass bf16 HMMA top-2 block winners + exact fp32 rescore
    split_hi_kernel<<<(BSx*Dx)/256, 256>>>(hs, ah, BSx*Dx);
    split_hi_kernel<<<(Mx*Dx)/256, 256>>>(mem, memh, Mx*Dx);
    knn_bf16_kernel<<<dim3(Mx/128, BSx/128), 128, GS_SMEM>>>(ah, memh);
    knn_select_kernel<<<BSx, 128>>>(hs, mem);

    // 2. gated L2 mix
    mix_kernel<<<BSx, 256>>>(hs, mem, gatelogit);

    // 3. RMS norm 1 -> act splits
    rmsnorm_split_kernel<<<BSx, 256>>>(merged, r1, ah, al);

    // 4. QKV projections (HMMA)
    gemm_bf16_kernel<<<dim3(Dx/128, BSx/128), 128, GS_SMEM>>>(ah, al, wqh, wql, nullptr, q, Dx, Dx);
    gemm_bf16_kernel<<<dim3(Dx/128, BSx/128), 128, GS_SMEM>>>(ah, al, wkh, wkl, nullptr, k, Dx, Dx);
    gemm_bf16_kernel<<<dim3(Dx/128, BSx/128), 128, GS_SMEM>>>(ah, al, wvh, wvl, nullptr, v, Dx, Dx);

    // 5. RoPE
    rope_kernel<<<(BSx * Hx * 64) / 256, 256>>>(pos);

    // 6. flash attention (writes ctx hi/lo split directly)
    attn_kernel<<<dim3(Sx/64, Hx, Bx), 256, att_smem>>>();

    // 7. output projection + residual
    gemm_bf16_kernel<<<dim3(Dx/128, BSx/128), 128, GS_SMEM>>>(ah, al, woh, wol, merged, xattn, Dx, Dx);

    // 8. RMS norm 2 -> act splits
    rmsnorm_split_kernel<<<BSx, 256>>>(xattn, r2, ah, al);

    // 9. MLP (HMMA)
    gemm_bf16_kernel<<<dim3(Fx/128, BSx/128), 128, GS_SMEM>>>(ah, al, wgh, wgl, nullptr, gbuf, Fx, Dx);
    gemm_bf16_kernel<<<dim3(Fx/128, BSx/128), 128, GS_SMEM>>>(ah, al, wuh, wul, nullptr, ubuf, Fx, Dx);
    silu_mul_split_kernel<<<(int)(((size_t)BSx*Fx)/256), 256>>>();
    gemm_bf16_kernel<<<dim3(Dx/128, BSx/128), 128, GS_SMEM>>>(ah, al, wdh, wdl, xattn, out, Dx, Fx);
}